// round 1
// baseline (speedup 1.0000x reference)
#include <cuda_runtime.h>

// Problem constants (fixed shapes per reference setup_inputs)
#define BB    4
#define NPTS  16384
#define KNN   16
#define CIN   64
#define CF    67          // 3 + 64 concat channels
#define CP    68          // padded row length (16B-aligned rows)
#define COUT  128
#define TP    32          // points per CTA
#define NTHR  256

// Scratch (static device globals — no runtime allocation)
__device__ float g_featsCL[(size_t)BB * NPTS * CP];   // [B][N][68] point-major concat(xyz, features)
__device__ float g_LT[(size_t)(16 * CF) * COUT];      // [1072][128] = lin_w transposed

// ---------------------------------------------------------------------------
// Prep A: channel-major [B,C,N] -> point-major [B,N,68] (col 67 zero pad)
// ---------------------------------------------------------------------------
__global__ void prep_feats(const float* __restrict__ xyz, const float* __restrict__ feats) {
    __shared__ float tile[CP][64];
    const int b  = blockIdx.y;
    const int n0 = blockIdx.x * 64;
    for (int i = threadIdx.x; i < CP * 64; i += NTHR) {
        int c = i >> 6, nn = i & 63;
        float v = 0.f;
        if (c < 3)       v = xyz[((size_t)b * 3 + c) * NPTS + n0 + nn];
        else if (c < CF) v = feats[((size_t)b * CIN + (c - 3)) * NPTS + n0 + nn];
        tile[c][nn] = v;
    }
    __syncthreads();
    for (int i = threadIdx.x; i < 64 * CP; i += NTHR) {
        int nn = i / CP, c = i - nn * CP;
        g_featsCL[((size_t)b * NPTS + n0 + nn) * CP + c] = tile[c][nn];
    }
}

// ---------------------------------------------------------------------------
// Prep B: lin_w [128][1072] -> g_LT [1072][128]
// ---------------------------------------------------------------------------
__global__ void prep_lt(const float* __restrict__ lin_w) {
    __shared__ float t[32][33];
    const int j0 = blockIdx.x * 32;   // column in lin_w (K dim, 0..1071)
    const int o0 = blockIdx.y * 32;   // row (output channel)
    const int lx = threadIdx.x & 31, ly = threadIdx.x >> 5;   // 256 thr: ly 0..7
    for (int r = ly; r < 32; r += 8) {
        int j = j0 + lx;
        t[r][lx] = (j < 16 * CF) ? lin_w[(size_t)(o0 + r) * (16 * CF) + j] : 0.f;
    }
    __syncthreads();
    for (int r = ly; r < 32; r += 8) {
        int j = j0 + r;
        if (j < 16 * CF) g_LT[(size_t)j * COUT + o0 + lx] = t[lx][r];
    }
}

// ---------------------------------------------------------------------------
// Main fused kernel: gather + weight-net + per-w aggregation + 128x32 GEMM tile
// ---------------------------------------------------------------------------
__device__ __forceinline__ void ffma2(unsigned long long& d, unsigned long long a, unsigned long long b) {
    asm("fma.rn.f32x2 %0, %1, %2, %0;" : "+l"(d) : "l"(a), "l"(b));
}

// smem float counts
#define SM_FEATS  (TP * KNN * CP)          // 34816
#define SM_WT     (TP * KNN * 16)          // 8192
#define SM_AGG2   (CF * 34 * 2)            // 4556 (67 rows of 34 float2, value-duplicated)
#define SM_IDX    (TP * KNN)               // 512 (ints)
#define SM_CXYZ   (TP * 4)                 // 128
#define SM_PAR    176                      // w1(24) b1(8) w2(128) b2(16)
#define SM_TOTALF (SM_FEATS + SM_WT + SM_AGG2 + SM_IDX + SM_CXYZ + SM_PAR)
#define SMEM_BYTES (SM_TOTALF * 4)

__global__ __launch_bounds__(NTHR, 1)
void pc_main(const int*   __restrict__ knn,
             const float* __restrict__ w1, const float* __restrict__ b1,
             const float* __restrict__ w2, const float* __restrict__ b2,
             const float* __restrict__ lin_b,
             float*       __restrict__ out)
{
    extern __shared__ float sm[];
    float*  sFeats = sm;                                   // [TP][KNN][CP]
    float*  sWt    = sm + SM_FEATS;                        // [TP][KNN][16]  (wt[p][k][w])
    float2* sAGG   = (float2*)(sm + SM_FEATS + SM_WT);     // [67][34] dup-pairs
    float*  sTail  = (float*)(sAGG + CF * 34);
    int*    sIdx   = (int*)sTail;                          // [TP][KNN]
    float*  sCxyz  = sTail + SM_IDX;                       // [TP][4]
    float*  sPar   = sCxyz + SM_CXYZ;                      // 176 params

    const int tid = threadIdx.x;
    const int b   = blockIdx.x >> 9;              // 512 blocks per batch
    const int pb  = (blockIdx.x & 511) * TP;
    const size_t fbase = (size_t)b * NPTS;

    // ---- phase 0: params, knn indices, center xyz ----
    if (tid < SM_PAR) {
        float v;
        if      (tid < 24)  v = w1[tid];
        else if (tid < 32)  v = b1[tid - 24];
        else if (tid < 160) v = w2[tid - 32];
        else                v = b2[tid - 160];
        sPar[tid] = v;
    }
    for (int i = tid; i < TP * KNN; i += NTHR)
        sIdx[i] = knn[(fbase + pb + (i >> 4)) * KNN + (i & 15)];
    if (tid < TP * 4) {
        int p = tid >> 2, c = tid & 3;
        sCxyz[tid] = (c < 3) ? g_featsCL[(fbase + pb + p) * CP + c] : 0.f;
    }
    __syncthreads();

    // ---- phase 1: gather neighbor rows (contiguous 272B each) ----
    for (int i = tid; i < TP * KNN * 17; i += NTHR) {
        int row = i / 17, c4 = i - row * 17;
        int gi  = sIdx[row];
        float4 v = *(const float4*)&g_featsCL[(fbase + gi) * CP + c4 * 4];
        *(float4*)&sFeats[row * CP + c4 * 4] = v;
    }

    // ---- phase 2: weight-net (3 -> 8 -> 16, leaky 0.1) per (p,k) ----
    {
        const float* W1 = sPar;       const float* B1 = sPar + 24;
        const float* W2 = sPar + 32;  const float* B2 = sPar + 160;
        for (int r = tid; r < TP * KNN; r += NTHR) {
            int p  = r >> 4;
            int gi = sIdx[r];
            const float* nb = &g_featsCL[(fbase + gi) * CP];
            float dx = nb[0] - sCxyz[p * 4 + 0];
            float dy = nb[1] - sCxyz[p * 4 + 1];
            float dz = nb[2] - sCxyz[p * 4 + 2];
            float h[8];
#pragma unroll
            for (int j = 0; j < 8; j++) {
                float v = W1[j*3]*dx + W1[j*3+1]*dy + W1[j*3+2]*dz + B1[j];
                h[j] = fmaxf(v, 0.1f * v);
            }
            float* wo = &sWt[r * 16];
#pragma unroll
            for (int wv = 0; wv < 16; wv++) {
                float s = B2[wv];
#pragma unroll
                for (int j = 0; j < 8; j++) s += W2[wv*8 + j] * h[j];
                wo[wv] = fmaxf(s, 0.1f * s);
            }
        }
    }
    __syncthreads();

    // ---- main loop: for each of 16 weight rows, build AGGw then GEMM-accumulate ----
    const int to = tid & 31;   // output-channel group: o = 4*to + {0..3}
    const int tp = tid >> 5;   // point group:          p = 4*tp + {0..3}
    unsigned long long acc[4][2];   // acc[pj][oi] packs (o even, o odd) pair
#pragma unroll
    for (int j = 0; j < 4; j++) { acc[j][0] = 0ull; acc[j][1] = 0ull; }

    for (int w16 = 0; w16 < 16; w16++) {
        // AGGw[c][p] = sum_k wt[p][k][w16] * feats[p][k][c], stored duplicated
        for (int i = tid; i < TP * 17; i += NTHR) {
            int p = i / 17, c4 = i - p * 17;
            const float* fb = &sFeats[p * KNN * CP + c4 * 4];
            const float* wb = &sWt[p * KNN * 16 + w16];
            float a0 = 0.f, a1 = 0.f, a2 = 0.f, a3 = 0.f;
#pragma unroll
            for (int k = 0; k < KNN; k++) {
                float wv = wb[k * 16];
                float4 f = *(const float4*)(fb + k * CP);
                a0 += wv * f.x; a1 += wv * f.y; a2 += wv * f.z; a3 += wv * f.w;
            }
            int c = c4 * 4;
            sAGG[c * 34 + p] = make_float2(a0, a0);
            if (c + 1 < CF) sAGG[(c + 1) * 34 + p] = make_float2(a1, a1);
            if (c + 2 < CF) sAGG[(c + 2) * 34 + p] = make_float2(a2, a2);
            if (c + 3 < CF) sAGG[(c + 3) * 34 + p] = make_float2(a3, a3);
        }
        __syncthreads();

        // GEMM: out[4to..+3][4tp..+3] += LT[w16*67+c][o] * AGGw[c][p]
        const ulonglong2* lrow = (const ulonglong2*)&g_LT[(size_t)(w16 * CF) * COUT + 4 * to];
        const ulonglong2* arow = (const ulonglong2*)sAGG + 2 * tp;
#pragma unroll 4
        for (int c = 0; c < CF; c++) {
            ulonglong2 lv  = lrow[(size_t)c * (COUT / 4)];  // (o0,o1),(o2,o3)
            ulonglong2 a01 = arow[c * 17];                  // dup(p0), dup(p1)
            ulonglong2 a23 = arow[c * 17 + 1];              // dup(p2), dup(p3)
            ffma2(acc[0][0], lv.x, a01.x); ffma2(acc[0][1], lv.y, a01.x);
            ffma2(acc[1][0], lv.x, a01.y); ffma2(acc[1][1], lv.y, a01.y);
            ffma2(acc[2][0], lv.x, a23.x); ffma2(acc[2][1], lv.y, a23.x);
            ffma2(acc[3][0], lv.x, a23.y); ffma2(acc[3][1], lv.y, a23.y);
        }
        __syncthreads();
    }

    // ---- epilogue: stage [128][32] tile in smem, write coalesced ----
    float* sOut = sFeats;  // reuse; [128][33]
#pragma unroll
    for (int j = 0; j < 4; j++) {
        int p = 4 * tp + j;
#pragma unroll
        for (int i = 0; i < 2; i++) {
            int o = 4 * to + 2 * i;
            float lo = __uint_as_float((unsigned)(acc[j][i] & 0xffffffffull));
            float hi = __uint_as_float((unsigned)(acc[j][i] >> 32));
            sOut[o * 33 + p]       = lo;
            sOut[(o + 1) * 33 + p] = hi;
        }
    }
    __syncthreads();
    for (int i = tid; i < COUT * TP; i += NTHR) {
        int o = i >> 5, p = i & 31;
        float v = sOut[o * 33 + p] + __ldg(&lin_b[o]);
        out[((size_t)b * COUT + o) * NPTS + pb + p] = fmaxf(v, 0.1f * v);
    }
}

// ---------------------------------------------------------------------------
extern "C" void kernel_launch(void* const* d_in, const int* in_sizes, int n_in,
                              void* d_out, int out_size) {
    const float* xyz   = (const float*)d_in[0];
    const float* feats = (const float*)d_in[1];
    const int*   knn   = (const int*)d_in[2];
    const float* w1    = (const float*)d_in[3];
    const float* b1    = (const float*)d_in[4];
    const float* w2    = (const float*)d_in[5];
    const float* b2    = (const float*)d_in[6];
    const float* lin_w = (const float*)d_in[7];
    const float* lin_b = (const float*)d_in[8];
    float* out = (float*)d_out;

    cudaFuncSetAttribute(pc_main, cudaFuncAttributeMaxDynamicSharedMemorySize, SMEM_BYTES);

    prep_feats<<<dim3(NPTS / 64, BB), NTHR>>>(xyz, feats);
    prep_lt<<<dim3((16 * CF + 31) / 32, COUT / 32), NTHR>>>(lin_w);
    pc_main<<<BB * NPTS / TP, NTHR, SMEM_BYTES>>>(knn, w1, b1, w2, b2, lin_b, out);
}

// round 7
// speedup vs baseline: 4.1272x; 4.1272x over previous
#include <cuda_runtime.h>
#include <cuda_bf16.h>
#include <cstdint>

// ---------------- problem constants ----------------
#define BB    4
#define NPTS  16384
#define KNN   16
#define CIN   64
#define CF    67
#define CP    68          // padded channels (col 67 == 0)
#define COUT  128
#define TP    32          // points per CTA
#define NTHR  256
#define NCH   17          // 1088/64 k-chunks of 64

// ---------------- global scratch ----------------
__device__ float g_featsCL[(size_t)BB * NPTS * CP];        // [B][N][68] point-major
// LT bf16 hi/lo planes in HMMA A-fragment order: [ch][warp][kstep][lane][4 u32]
__device__ __align__(128) uint32_t g_LTh[NCH * 4096];
__device__ __align__(128) uint32_t g_LTl[NCH * 4096];

// ---------------- smem layout (bytes) ----------------
#define SM_AGGH 0          // 69632: AGG hi plane (B-fragment order)
#define SM_AGGL 69632      // 69632: AGG lo plane
#define SM_STG  139264     // 65536: 2 stages x (LThi 16K + LTlo 16K)
#define SM_WT   204800     // 8192: per-warp weight-net out [8][256]f
#define SM_IDX  212992     // 512:  per-warp knn idx [8][16]i
#define SM_PAR  213504     // 704:  w1(24) b1(8) w2(128) b2(16)
#define SM_BAR  214208     // 16:   2 mbarriers
#define SMEM_BYTES 214272

// ---------------- PTX helpers ----------------
__device__ __forceinline__ uint32_t smem_u32(const void* p) {
    uint32_t a;
    asm("{ .reg .u64 t; cvta.to.shared.u64 t, %1; cvt.u32.u64 %0, t; }" : "=r"(a) : "l"(p));
    return a;
}
#define MBAR_INIT(a, c)   asm volatile("mbarrier.init.shared.b64 [%0], %1;" :: "r"(a), "r"(c) : "memory")
#define MBAR_EXPECT(a, n) asm volatile("mbarrier.arrive.expect_tx.shared.b64 _, [%0], %1;" :: "r"(a), "r"(n) : "memory")
#define MBAR_INVAL(a)     asm volatile("mbarrier.inval.shared.b64 [%0];" :: "r"(a) : "memory")

__device__ __forceinline__ void mbar_wait(uint32_t mbar, uint32_t parity) {
    asm volatile(
        "{\n\t.reg .pred P1;\n\t"
        "WAIT_LOOP_%=:\n\t"
        "mbarrier.try_wait.parity.acquire.cta.shared::cta.b64 P1, [%0], %1, 0x989680;\n\t"
        "@P1 bra.uni WAIT_DONE_%=;\n\t"
        "bra.uni WAIT_LOOP_%=;\n\t"
        "WAIT_DONE_%=:\n\t}"
        :: "r"(mbar), "r"(parity) : "memory");
}
__device__ __forceinline__ void bulk_cp(uint32_t dst_smem, const void* src_gmem, uint32_t bytes, uint32_t mbar) {
    asm volatile(
        "cp.async.bulk.shared::cluster.global.mbarrier::complete_tx::bytes [%0], [%1], %2, [%3];"
        :: "r"(dst_smem), "l"((unsigned long long)src_gmem), "r"(bytes), "r"(mbar) : "memory");
}
__device__ __forceinline__ void mma16816(float* c, uint32_t a0, uint32_t a1, uint32_t a2, uint32_t a3,
                                         uint32_t b0, uint32_t b1) {
    asm volatile(
        "mma.sync.aligned.m16n8k16.row.col.f32.bf16.bf16.f32 "
        "{%0,%1,%2,%3}, {%4,%5,%6,%7}, {%8,%9}, {%0,%1,%2,%3};"
        : "+f"(c[0]), "+f"(c[1]), "+f"(c[2]), "+f"(c[3])
        : "r"(a0), "r"(a1), "r"(a2), "r"(a3), "r"(b0), "r"(b1));
}

// ---------------------------------------------------------------------------
// Prep A: channel-major [B,C,N] -> point-major [B,N,68] (col 67 zero)
// ---------------------------------------------------------------------------
__global__ void prep_feats(const float* __restrict__ xyz, const float* __restrict__ feats) {
    __shared__ float tile[CP][64];
    const int b  = blockIdx.y;
    const int n0 = blockIdx.x * 64;
    for (int i = threadIdx.x; i < CP * 64; i += NTHR) {
        int c = i >> 6, nn = i & 63;
        float v = 0.f;
        if (c < 3)       v = xyz[((size_t)b * 3 + c) * NPTS + n0 + nn];
        else if (c < CF) v = feats[((size_t)b * CIN + (c - 3)) * NPTS + n0 + nn];
        tile[c][nn] = v;
    }
    __syncthreads();
    for (int i = threadIdx.x; i < 64 * CP; i += NTHR) {
        int nn = i / CP, c = i - nn * CP;
        g_featsCL[((size_t)b * NPTS + n0 + nn) * CP + c] = tile[c][nn];
    }
}

// ---------------------------------------------------------------------------
// Prep B: lin_w -> bf16 hi/lo planes in A-fragment order [ch][w][ks][lane][r]
// K index = w16*68 + c (c==67 -> 0 pad)
// ---------------------------------------------------------------------------
__global__ void prep_lt(const float* __restrict__ lin_w) {
    int idx = blockIdx.x * NTHR + threadIdx.x;
    if (idx >= NCH * 4096) return;
    int r    = idx & 3;
    int lane = (idx >> 2) & 31;
    int ks   = (idx >> 7) & 3;
    int w    = (idx >> 9) & 7;
    int ch   = idx >> 12;
    int row = (lane >> 2) + ((r & 1) ? 8 : 0);
    int fk  = (lane & 3) * 2 + ((r >= 2) ? 8 : 0);
    int o   = w * 16 + row;
    uint32_t hi = 0, lo = 0;
#pragma unroll
    for (int e = 0; e < 2; e++) {
        int kg = ch * 64 + ks * 16 + fk + e;
        int wr = kg / CP, c = kg - wr * CP;
        float v = (c < CF) ? lin_w[(size_t)o * (16 * CF) + wr * CF + c] : 0.f;
        __nv_bfloat16 h = __float2bfloat16(v);
        __nv_bfloat16 l = __float2bfloat16(v - __bfloat162float(h));
        hi |= (uint32_t)__bfloat16_as_ushort(h) << (16 * e);
        lo |= (uint32_t)__bfloat16_as_ushort(l) << (16 * e);
    }
    g_LTh[idx] = hi;
    g_LTl[idx] = lo;
}

// ---------------------------------------------------------------------------
// Main fused kernel: gather + weight-net + AGG fragments + streamed HMMA GEMM
// ---------------------------------------------------------------------------
__global__ __launch_bounds__(NTHR, 1)
void pc_main(const int*   __restrict__ knn,
             const float* __restrict__ w1, const float* __restrict__ b1,
             const float* __restrict__ w2, const float* __restrict__ b2,
             const float* __restrict__ lin_b,
             float*       __restrict__ out)
{
    extern __shared__ __align__(1024) char smem[];
    const uint32_t sb = smem_u32(smem);
    const int tid  = threadIdx.x;
    const int warp = tid >> 5;
    const int lane = tid & 31;
    const int b    = blockIdx.x >> 9;
    const int pb   = (blockIdx.x & 511) * TP;
    const size_t fb = (size_t)b * NPTS;
    const uint32_t barF0 = sb + SM_BAR, barF1 = sb + SM_BAR + 8;

    // params + mbarrier init
    float* sPar = (float*)(smem + SM_PAR);
    if (tid < 176) {
        float v;
        if      (tid < 24)  v = w1[tid];
        else if (tid < 32)  v = b1[tid - 24];
        else if (tid < 160) v = w2[tid - 32];
        else                v = b2[tid - 160];
        sPar[tid] = v;
    }
    if (tid == 0) { MBAR_INIT(barF0, 1); MBAR_INIT(barF1, 1); }
    __syncthreads();

    // prologue: prefetch LT chunks 0,1 (overlaps phase 1)
    if (tid == 0) {
        MBAR_EXPECT(barF0, 32768);
        bulk_cp(sb + SM_STG,                 g_LTh,        16384, barF0);
        bulk_cp(sb + SM_STG + 16384,         g_LTl,        16384, barF0);
        MBAR_EXPECT(barF1, 32768);
        bulk_cp(sb + SM_STG + 32768,         g_LTh + 4096, 16384, barF1);
        bulk_cp(sb + SM_STG + 32768 + 16384, g_LTl + 4096, 16384, barF1);
    }

    // ---- phase 1: gather + weight-net + per-point AGG -> bf16 hi/lo fragments ----
    {
        float* myWt  = (float*)(smem + SM_WT) + warp * 256;
        int*   myIdx = (int*)(smem + SM_IDX) + warp * 16;
        const float* W1 = sPar;       const float* B1 = sPar + 24;
        const float* W2 = sPar + 32;  const float* B2 = sPar + 160;
        __nv_bfloat16* aggH = (__nv_bfloat16*)(smem + SM_AGGH);
        __nv_bfloat16* aggL = (__nv_bfloat16*)(smem + SM_AGGL);

        for (int r = 0; r < 4; r++) {
            const int p = r * 8 + warp;
            if (lane < 16) myIdx[lane] = knn[(fb + pb + p) * KNN + lane];
            __syncwarp();
            const float* crow = g_featsCL + (fb + pb + p) * CP;
            const float cx = crow[0], cy = crow[1], cz = crow[2];
            {
                const int k = lane >> 1, half = lane & 1;
                const float* nrow = g_featsCL + (fb + myIdx[k]) * CP;
                const float dx = nrow[0] - cx, dy = nrow[1] - cy, dz = nrow[2] - cz;
                float h[8];
#pragma unroll
                for (int j = 0; j < 8; j++) {
                    float v = W1[j*3]*dx + W1[j*3+1]*dy + W1[j*3+2]*dz + B1[j];
                    h[j] = fmaxf(v, 0.1f * v);
                }
#pragma unroll
                for (int wv = 0; wv < 8; wv++) {
                    int w = half * 8 + wv;
                    float s = B2[w];
#pragma unroll
                    for (int j = 0; j < 8; j++) s += W2[w*8 + j] * h[j];
                    myWt[k * 16 + w] = fmaxf(s, 0.1f * s);
                }
            }
            __syncwarp();

            float a0[16], a1[16], a2[16];
#pragma unroll
            for (int w = 0; w < 16; w++) { a0[w] = 0.f; a1[w] = 0.f; a2[w] = 0.f; }
#pragma unroll
            for (int k = 0; k < KNN; k++) {
                const float* nrow = g_featsCL + (fb + myIdx[k]) * CP;
                float f0 = nrow[lane];
                float f1 = nrow[32 + lane];
                float f2 = (lane < 4) ? nrow[64 + lane] : 0.f;
#pragma unroll
                for (int w4 = 0; w4 < 4; w4++) {
                    float4 wt4 = *(const float4*)&myWt[k * 16 + w4 * 4];
                    a0[w4*4+0] += wt4.x*f0; a1[w4*4+0] += wt4.x*f1; a2[w4*4+0] += wt4.x*f2;
                    a0[w4*4+1] += wt4.y*f0; a1[w4*4+1] += wt4.y*f1; a2[w4*4+1] += wt4.y*f2;
                    a0[w4*4+2] += wt4.z*f0; a1[w4*4+2] += wt4.z*f1; a2[w4*4+2] += wt4.z*f2;
                    a0[w4*4+3] += wt4.w*f0; a1[w4*4+3] += wt4.w*f1; a2[w4*4+3] += wt4.w*f2;
                }
            }
            // scatter into B-fragment-ordered AGG planes
            const int n = p & 7, nb = p >> 3;
#pragma unroll
            for (int w = 0; w < 16; w++) {
#pragma unroll
                for (int part = 0; part < 3; part++) {
                    if (part == 2 && lane >= 4) break;
                    int kg = w * CP + part * 32 + lane;
                    float v = (part == 0) ? a0[w] : (part == 1) ? a1[w] : a2[w];
                    int ch = kg >> 6, kl = kg & 63;
                    int ks = kl >> 4, kl2 = kl & 15;
                    uint32_t off = (uint32_t)(((ch * 4 + ks) * 4 + nb) * 256
                                   + (n * 4 + ((kl2 >> 1) & 3)) * 8 + (kl2 >> 3) * 4 + (kl2 & 1) * 2);
                    __nv_bfloat16 h = __float2bfloat16(v);
                    __nv_bfloat16 l = __float2bfloat16(v - __bfloat162float(h));
                    *(__nv_bfloat16*)((char*)aggH + off) = h;
                    *(__nv_bfloat16*)((char*)aggL + off) = l;
                }
            }
            __syncwarp();
        }
    }
    __syncthreads();

    // ---- phase 2: streamed-LT HMMA GEMM, 3 bf16 planes ----
    float acc[16];
#pragma unroll
    for (int i = 0; i < 16; i++) acc[i] = 0.f;

    for (int ch = 0; ch < NCH; ch++) {
        const int s = ch & 1;
        const uint32_t full = s ? barF1 : barF0;
        mbar_wait(full, (ch >> 1) & 1);
        const uint32_t Ahi = sb + SM_STG + s * 32768 + warp * 2048;
#pragma unroll
        for (int pl = 0; pl < 3; pl++) {
            const uint32_t A  = (pl == 2) ? (Ahi + 16384) : Ahi;
            const uint32_t Bb = sb + ((pl == 1) ? SM_AGGL : SM_AGGH) + ch * 4096 + lane * 8;
#pragma unroll
            for (int ks = 0; ks < 4; ks++) {
                uint32_t a0, a1, a2, a3;
                asm volatile("ld.shared.v4.u32 {%0,%1,%2,%3}, [%4];"
                             : "=r"(a0), "=r"(a1), "=r"(a2), "=r"(a3)
                             : "r"(A + ks * 512 + lane * 16));
#pragma unroll
                for (int nb = 0; nb < 4; nb++) {
                    uint32_t b0, b1;
                    asm volatile("ld.shared.v2.u32 {%0,%1}, [%2];"
                                 : "=r"(b0), "=r"(b1)
                                 : "r"(Bb + ks * 1024 + nb * 256));
                    mma16816(acc + nb * 4, a0, a1, a2, a3, b0, b1);
                }
            }
        }
        __syncthreads();
        if (tid == 0 && ch <= NCH - 3) {
            MBAR_EXPECT(full, 32768);
            uint32_t dst = sb + SM_STG + s * 32768;
            bulk_cp(dst,         g_LTh + (ch + 2) * 4096, 16384, full);
            bulk_cp(dst + 16384, g_LTl + (ch + 2) * 4096, 16384, full);
        }
    }

    // ---- epilogue: bias + leaky + float2 stores ----
    {
        const int row = lane >> 2, col2 = (lane & 3) * 2;
#pragma unroll
        for (int nb = 0; nb < 4; nb++) {
#pragma unroll
            for (int h = 0; h < 2; h++) {
                const int o = warp * 16 + row + h * 8;
                const float bias = __ldg(&lin_b[o]);
                const int p = nb * 8 + col2;
                float x0 = acc[nb*4 + h*2 + 0] + bias;
                float x1 = acc[nb*4 + h*2 + 1] + bias;
                float2 v = make_float2(fmaxf(x0, 0.1f * x0), fmaxf(x1, 0.1f * x1));
                *(float2*)(out + ((size_t)b * COUT + o) * NPTS + pb + p) = v;
            }
        }
    }
    __syncthreads();
    if (tid == 0) { MBAR_INVAL(barF0); MBAR_INVAL(barF1); }
}

// ---------------------------------------------------------------------------
extern "C" void kernel_launch(void* const* d_in, const int* in_sizes, int n_in,
                              void* d_out, int out_size) {
    const float* xyz   = (const float*)d_in[0];
    const float* feats = (const float*)d_in[1];
    const int*   knn   = (const int*)d_in[2];
    const float* w1    = (const float*)d_in[3];
    const float* b1    = (const float*)d_in[4];
    const float* w2    = (const float*)d_in[5];
    const float* b2    = (const float*)d_in[6];
    const float* lin_w = (const float*)d_in[7];
    const float* lin_b = (const float*)d_in[8];
    float* out = (float*)d_out;

    cudaFuncSetAttribute(pc_main, cudaFuncAttributeMaxDynamicSharedMemorySize, SMEM_BYTES);

    prep_feats<<<dim3(NPTS / 64, BB), NTHR>>>(xyz, feats);
    prep_lt<<<(NCH * 4096 + NTHR - 1) / NTHR, NTHR>>>(lin_w);
    pc_main<<<BB * NPTS / TP, NTHR, SMEM_BYTES>>>(knn, w1, b1, w2, b2, lin_b, out);
}

// round 8
// speedup vs baseline: 4.9286x; 1.1942x over previous
#include <cuda_runtime.h>
#include <cuda_fp16.h>
#include <cstdint>

// ---------------- problem constants ----------------
#define BB    4
#define NPTS  16384
#define KNN   16
#define CIN   64
#define CF    67
#define CP    72          // padded channels (cols 67..71 zero)
#define COUT  128
#define TP    64          // points per CTA
#define NTHR  256
#define NCH   17          // 1088/64 k-chunks

// ---------------- global scratch ----------------
__device__ float g_featsCL[(size_t)BB * NPTS * CP];     // [B][N][72] point-major
// LT fp16 single plane, HMMA A-frag order: [ch][w][ks][lane][4 u32]
__device__ __align__(128) uint32_t g_LT[NCH * 4096];

// ---------------- smem layout (bytes) ----------------
#define SM_AGG  0          // 139264: AGG fp16, big-GEMM B-frag order [ch][ks][nb][256B]
#define SM_STG  139264     // 65536:  4 stages x 16KB LT chunk
#define SM_WT   204800     // 8704:   8 warps x 272 floats (stride-17 wt scratch)
#define SM_IDX  213504     // 512:    8 warps x 16 ints
#define SM_PAR  214016     // 704:    w1(24) b1(8) w2(128) b2(16)
#define SM_BAR  214720     // 64:     4 mbarriers
#define SMEM_BYTES 214784

// ---------------- PTX helpers ----------------
__device__ __forceinline__ uint32_t smem_u32(const void* p) {
    uint32_t a;
    asm("{ .reg .u64 t; cvta.to.shared.u64 t, %1; cvt.u32.u64 %0, t; }" : "=r"(a) : "l"(p));
    return a;
}
#define MBAR_INIT(a, c)   asm volatile("mbarrier.init.shared.b64 [%0], %1;" :: "r"(a), "r"(c) : "memory")
#define MBAR_EXPECT(a, n) asm volatile("mbarrier.arrive.expect_tx.shared.b64 _, [%0], %1;" :: "r"(a), "r"(n) : "memory")
#define MBAR_INVAL(a)     asm volatile("mbarrier.inval.shared.b64 [%0];" :: "r"(a) : "memory")

__device__ __forceinline__ void mbar_wait(uint32_t mbar, uint32_t parity) {
    asm volatile(
        "{\n\t.reg .pred P1;\n\t"
        "WAIT_LOOP_%=:\n\t"
        "mbarrier.try_wait.parity.acquire.cta.shared::cta.b64 P1, [%0], %1, 0x989680;\n\t"
        "@P1 bra.uni WAIT_DONE_%=;\n\t"
        "bra.uni WAIT_LOOP_%=;\n\t"
        "WAIT_DONE_%=:\n\t}"
        :: "r"(mbar), "r"(parity) : "memory");
}
__device__ __forceinline__ void bulk_cp(uint32_t dst_smem, const void* src_gmem, uint32_t bytes, uint32_t mbar) {
    asm volatile(
        "cp.async.bulk.shared::cluster.global.mbarrier::complete_tx::bytes [%0], [%1], %2, [%3];"
        :: "r"(dst_smem), "l"((unsigned long long)src_gmem), "r"(bytes), "r"(mbar) : "memory");
}
__device__ __forceinline__ void mma16816h(float* c, uint32_t a0, uint32_t a1, uint32_t a2, uint32_t a3,
                                          uint32_t b0, uint32_t b1) {
    asm volatile(
        "mma.sync.aligned.m16n8k16.row.col.f32.f16.f16.f32 "
        "{%0,%1,%2,%3}, {%4,%5,%6,%7}, {%8,%9}, {%0,%1,%2,%3};"
        : "+f"(c[0]), "+f"(c[1]), "+f"(c[2]), "+f"(c[3])
        : "r"(a0), "r"(a1), "r"(a2), "r"(a3), "r"(b0), "r"(b1));
}
__device__ __forceinline__ uint32_t packh2(float a, float b) {
    __half2 h = __floats2half2_rn(a, b);   // low = a, high = b
    return *(uint32_t*)&h;
}

// ---------------------------------------------------------------------------
// Prep A: channel-major [B,C,N] -> point-major [B,N,72] (cols 67..71 zero)
// ---------------------------------------------------------------------------
__global__ void prep_feats(const float* __restrict__ xyz, const float* __restrict__ feats) {
    __shared__ float tile[CP][64];
    const int b  = blockIdx.y;
    const int n0 = blockIdx.x * 64;
    for (int i = threadIdx.x; i < CP * 64; i += NTHR) {
        int c = i >> 6, nn = i & 63;
        float v = 0.f;
        if (c < 3)       v = xyz[((size_t)b * 3 + c) * NPTS + n0 + nn];
        else if (c < CF) v = feats[((size_t)b * CIN + (c - 3)) * NPTS + n0 + nn];
        tile[c][nn] = v;
    }
    __syncthreads();
    for (int i = threadIdx.x; i < 64 * (CP / 4); i += NTHR) {
        int nn = i / (CP / 4), q = i - nn * (CP / 4);
        float4 v = make_float4(tile[q*4+0][nn], tile[q*4+1][nn], tile[q*4+2][nn], tile[q*4+3][nn]);
        *(float4*)&g_featsCL[((size_t)b * NPTS + n0 + nn) * CP + q * 4] = v;
    }
}

// ---------------------------------------------------------------------------
// Prep B: lin_w -> fp16 plane in A-frag order [ch][w][ks][lane][r]
// K index = w16*68 + c (c==67 -> 0 pad); lin_w inner = w*67 + c
// ---------------------------------------------------------------------------
__global__ void prep_lt(const float* __restrict__ lin_w) {
    int idx = blockIdx.x * NTHR + threadIdx.x;
    if (idx >= NCH * 4096) return;
    int r    = idx & 3;
    int lane = (idx >> 2) & 31;
    int ks   = (idx >> 7) & 3;
    int w    = (idx >> 9) & 7;
    int ch   = idx >> 12;
    int row = (lane >> 2) + ((r & 1) ? 8 : 0);
    int fk  = (lane & 3) * 2 + ((r >= 2) ? 8 : 0);
    int o   = w * 16 + row;
    float v[2];
#pragma unroll
    for (int e = 0; e < 2; e++) {
        int kg = ch * 64 + ks * 16 + fk + e;
        int wr = kg / 68, c = kg - wr * 68;
        v[e] = (c < CF) ? lin_w[(size_t)o * (16 * CF) + wr * CF + c] : 0.f;
    }
    g_LT[idx] = packh2(v[0], v[1]);
}

// ---------------------------------------------------------------------------
// AGG scatter into big-GEMM B-frag layout (verified formula from round 7)
// ---------------------------------------------------------------------------
__device__ __forceinline__ void store_agg(char* smem, int p, int w, int c, float v) {
    if (c >= 68) return;
    int kg = w * 68 + c;
    int ch = kg >> 6, kl = kg & 63;
    int ks = kl >> 4, kl2 = kl & 15;
    uint32_t off = (uint32_t)(((ch * 4 + ks) * 8 + (p >> 3)) * 256
                   + ((p & 7) * 4 + ((kl2 >> 1) & 3)) * 8 + (kl2 >> 3) * 4 + (kl2 & 1) * 2);
    *(__half*)(smem + SM_AGG + off) = __float2half_rn(v);
}

// ---------------------------------------------------------------------------
// Main fused kernel
// ---------------------------------------------------------------------------
__global__ __launch_bounds__(NTHR, 1)
void pc_main(const int*   __restrict__ knn,
             const float* __restrict__ w1, const float* __restrict__ b1,
             const float* __restrict__ w2, const float* __restrict__ b2,
             const float* __restrict__ lin_b,
             float*       __restrict__ out)
{
    extern __shared__ __align__(1024) char smem[];
    const uint32_t sb = smem_u32(smem);
    const int tid  = threadIdx.x;
    const int warp = tid >> 5;
    const int lane = tid & 31;
    const int b    = blockIdx.x >> 8;             // 256 CTAs per batch
    const int pb   = (blockIdx.x & 255) * TP;
    const size_t fb = (size_t)b * NPTS;

    // params + mbarrier init
    float* sPar = (float*)(smem + SM_PAR);
    if (tid < 176) {
        float v;
        if      (tid < 24)  v = w1[tid];
        else if (tid < 32)  v = b1[tid - 24];
        else if (tid < 160) v = w2[tid - 32];
        else                v = b2[tid - 160];
        sPar[tid] = v;
    }
    if (tid == 0) {
#pragma unroll
        for (int s = 0; s < 4; s++) MBAR_INIT(sb + SM_BAR + s * 8, 1);
    }
    __syncthreads();

    // prefetch LT chunks 0..3 (overlaps phase 1)
    if (tid == 0) {
#pragma unroll
        for (int s = 0; s < 4; s++) {
            MBAR_EXPECT(sb + SM_BAR + s * 8, 16384);
            bulk_cp(sb + SM_STG + s * 16384, g_LT + s * 4096, 16384, sb + SM_BAR + s * 8);
        }
    }

    // ---- phase 1: gather + weight-net + per-point inner MMA -> AGG fp16 ----
    {
        float* myWt  = (float*)(smem + SM_WT) + warp * 272;   // [k][17] stride-17
        int*   myIdx = (int*)(smem + SM_IDX) + warp * 16;
        const float* W1 = sPar;       const float* B1 = sPar + 24;
        const float* W2 = sPar + 32;  const float* B2 = sPar + 160;
        const int kp   = (lane & 3) * 2;
        const int wrow = lane >> 2;
        const int cl   = lane >> 2;

        for (int r = 0; r < 8; r++) {
            const int p = warp * 8 + r;      // nb = warp: AGG writes warp-disjoint
            if (lane < 16) myIdx[lane] = knn[(fb + pb + p) * KNN + lane];
            __syncwarp();

            // weight-net: lane -> (k = lane/2, half), 8 of 16 w each
            {
                const float* crow = g_featsCL + (fb + pb + p) * CP;
                const float cx = crow[0], cy = crow[1], cz = crow[2];
                const int k = lane >> 1, half = lane & 1;
                const float* nrow = g_featsCL + (fb + myIdx[k]) * CP;
                const float dx = nrow[0] - cx, dy = nrow[1] - cy, dz = nrow[2] - cz;
                float h[8];
#pragma unroll
                for (int j = 0; j < 8; j++) {
                    float v = W1[j*3]*dx + W1[j*3+1]*dy + W1[j*3+2]*dz + B1[j];
                    h[j] = fmaxf(v, 0.1f * v);
                }
#pragma unroll
                for (int wv = 0; wv < 8; wv++) {
                    int w = half * 8 + wv;
                    float s = B2[w];
#pragma unroll
                    for (int j = 0; j < 8; j++) s += W2[w*8 + j] * h[j];
                    myWt[k * 17 + w] = fmaxf(s, 0.1f * s);
                }
            }
            __syncwarp();

            // A fragment: A[w][k] = myWt[k*17 + w]
            uint32_t a0 = packh2(myWt[kp*17 + wrow],        myWt[(kp+1)*17 + wrow]);
            uint32_t a1 = packh2(myWt[kp*17 + wrow + 8],    myWt[(kp+1)*17 + wrow + 8]);
            uint32_t a2 = packh2(myWt[(kp+8)*17 + wrow],    myWt[(kp+9)*17 + wrow]);
            uint32_t a3 = packh2(myWt[(kp+8)*17 + wrow + 8], myWt[(kp+9)*17 + wrow + 8]);

            // B fragments: feats[k][c], c = cb*8 + lane/4, k rows via 4 gathered rows
            const float* r0p = g_featsCL + (fb + myIdx[kp])     * CP;
            const float* r1p = g_featsCL + (fb + myIdx[kp + 1]) * CP;
            const float* r2p = g_featsCL + (fb + myIdx[kp + 8]) * CP;
            const float* r3p = g_featsCL + (fb + myIdx[kp + 9]) * CP;
            uint32_t bb0[9], bb1[9];
#pragma unroll
            for (int cb = 0; cb < 9; cb++) {
                int c = cb * 8 + cl;
                bb0[cb] = packh2(r0p[c], r1p[c]);
                bb1[cb] = packh2(r2p[c], r3p[c]);
            }
            // 9 inner MMAs -> AGG[16w][72c] scatter (c>=68 dropped)
#pragma unroll
            for (int cb = 0; cb < 9; cb++) {
                float c4[4] = {0.f, 0.f, 0.f, 0.f};
                mma16816h(c4, a0, a1, a2, a3, bb0[cb], bb1[cb]);
                int cc = cb * 8 + (lane & 3) * 2;
                store_agg(smem, p, wrow,     cc,     c4[0]);
                store_agg(smem, p, wrow,     cc + 1, c4[1]);
                store_agg(smem, p, wrow + 8, cc,     c4[2]);
                store_agg(smem, p, wrow + 8, cc + 1, c4[3]);
            }
            __syncwarp();
        }
    }
    __syncthreads();

    // ---- phase 2: streamed-LT single-plane HMMA GEMM ----
    float acc[8][4];
#pragma unroll
    for (int nb = 0; nb < 8; nb++) { acc[nb][0] = acc[nb][1] = acc[nb][2] = acc[nb][3] = 0.f; }

    for (int ch = 0; ch < NCH; ch++) {
        const int s = ch & 3;
        mbar_wait(sb + SM_BAR + s * 8, (ch >> 2) & 1);
        const uint32_t A  = sb + SM_STG + s * 16384 + warp * 2048;
        const uint32_t Bb = sb + SM_AGG + ch * 8192 + lane * 8;
#pragma unroll
        for (int ks = 0; ks < 4; ks++) {
            uint32_t a0, a1, a2, a3;
            asm volatile("ld.shared.v4.u32 {%0,%1,%2,%3}, [%4];"
                         : "=r"(a0), "=r"(a1), "=r"(a2), "=r"(a3)
                         : "r"(A + ks * 512 + lane * 16));
#pragma unroll
            for (int nb = 0; nb < 8; nb++) {
                uint32_t b0, b1;
                asm volatile("ld.shared.v2.u32 {%0,%1}, [%2];"
                             : "=r"(b0), "=r"(b1)
                             : "r"(Bb + ks * 2048 + nb * 256));
                mma16816h(acc[nb], a0, a1, a2, a3, b0, b1);
            }
        }
        __syncthreads();
        if (tid == 0 && ch + 4 < NCH) {
            MBAR_EXPECT(sb + SM_BAR + s * 8, 16384);
            bulk_cp(sb + SM_STG + s * 16384, g_LT + (ch + 4) * 4096, 16384, sb + SM_BAR + s * 8);
        }
    }

    // ---- epilogue: bias + leaky + float2 stores ----
    {
        const int wrow = lane >> 2, pc2 = (lane & 3) * 2;
#pragma unroll
        for (int h = 0; h < 2; h++) {
            const int o = warp * 16 + wrow + h * 8;
            const float bias = __ldg(&lin_b[o]);
            float* orow = out + ((size_t)b * COUT + o) * NPTS + pb;
#pragma unroll
            for (int nb = 0; nb < 8; nb++) {
                float x0 = acc[nb][h*2 + 0] + bias;
                float x1 = acc[nb][h*2 + 1] + bias;
                float2 v = make_float2(fmaxf(x0, 0.1f * x0), fmaxf(x1, 0.1f * x1));
                *(float2*)(orow + nb * 8 + pc2) = v;
            }
        }
    }
    __syncthreads();
    if (tid == 0) {
#pragma unroll
        for (int s = 0; s < 4; s++) MBAR_INVAL(sb + SM_BAR + s * 8);
    }
}

// ---------------------------------------------------------------------------
extern "C" void kernel_launch(void* const* d_in, const int* in_sizes, int n_in,
                              void* d_out, int out_size) {
    const float* xyz   = (const float*)d_in[0];
    const float* feats = (const float*)d_in[1];
    const int*   knn   = (const int*)d_in[2];
    const float* w1    = (const float*)d_in[3];
    const float* b1    = (const float*)d_in[4];
    const float* w2    = (const float*)d_in[5];
    const float* b2    = (const float*)d_in[6];
    const float* lin_w = (const float*)d_in[7];
    const float* lin_b = (const float*)d_in[8];
    float* out = (float*)d_out;

    cudaFuncSetAttribute(pc_main, cudaFuncAttributeMaxDynamicSharedMemorySize, SMEM_BYTES);

    prep_feats<<<dim3(NPTS / 64, BB), NTHR>>>(xyz, feats);
    prep_lt<<<(NCH * 4096 + NTHR - 1) / NTHR, NTHR>>>(lin_w);
    pc_main<<<BB * NPTS / TP, NTHR, SMEM_BYTES>>>(knn, w1, b1, w2, b2, lin_b, out);
}

// round 9
// speedup vs baseline: 5.7170x; 1.1600x over previous
#include <cuda_runtime.h>
#include <cuda_fp16.h>
#include <cstdint>

// ---------------- problem constants ----------------
#define BB    4
#define NPTS  16384
#define KNN   16
#define CIN   64
#define CF    67
#define CP    72          // padded channels (cols 67..71 zero)
#define COUT  128
#define NTHR  256
#define NCH   17          // 1088/64 k-chunks
#define BLKB  17408       // bytes of AGG per 8-point block: 17ch * 4ks * 256B

// ---------------- global scratch ----------------
__device__ float g_featsCL[(size_t)BB * NPTS * CP];     // [B][N][72] point-major fp32
// LT fp16, HMMA A-frag order: [ch][w][ks][lane][4B*4]
__device__ __align__(128) uint32_t g_LT[NCH * 4096];
// AGG fp16, GEMM-B-frag order: [block(8192)][ch(17)][ks(4)][256B]
__device__ __align__(128) unsigned char g_AGG[(size_t)8192 * BLKB];

// ---------------- PTX helpers ----------------
__device__ __forceinline__ uint32_t smem_u32(const void* p) {
    uint32_t a;
    asm("{ .reg .u64 t; cvta.to.shared.u64 t, %1; cvt.u32.u64 %0, t; }" : "=r"(a) : "l"(p));
    return a;
}
#define MBAR_INIT(a, c)   asm volatile("mbarrier.init.shared.b64 [%0], %1;" :: "r"(a), "r"(c) : "memory")
#define MBAR_EXPECT(a, n) asm volatile("mbarrier.arrive.expect_tx.shared.b64 _, [%0], %1;" :: "r"(a), "r"(n) : "memory")
#define MBAR_INVAL(a)     asm volatile("mbarrier.inval.shared.b64 [%0];" :: "r"(a) : "memory")

__device__ __forceinline__ void mbar_wait(uint32_t mbar, uint32_t parity) {
    asm volatile(
        "{\n\t.reg .pred P1;\n\t"
        "WAIT_LOOP_%=:\n\t"
        "mbarrier.try_wait.parity.acquire.cta.shared::cta.b64 P1, [%0], %1, 0x989680;\n\t"
        "@P1 bra.uni WAIT_DONE_%=;\n\t"
        "bra.uni WAIT_LOOP_%=;\n\t"
        "WAIT_DONE_%=:\n\t}"
        :: "r"(mbar), "r"(parity) : "memory");
}
__device__ __forceinline__ void bulk_cp(uint32_t dst_smem, const void* src_gmem, uint32_t bytes, uint32_t mbar) {
    asm volatile(
        "cp.async.bulk.shared::cluster.global.mbarrier::complete_tx::bytes [%0], [%1], %2, [%3];"
        :: "r"(dst_smem), "l"((unsigned long long)src_gmem), "r"(bytes), "r"(mbar) : "memory");
}
__device__ __forceinline__ void bulk_st(void* dst_gmem, uint32_t src_smem, uint32_t bytes) {
    asm volatile(
        "cp.async.bulk.global.shared::cta.bulk_group [%0], [%1], %2;"
        :: "l"((unsigned long long)dst_gmem), "r"(src_smem), "r"(bytes) : "memory");
}
__device__ __forceinline__ void mma16816h(float* c, uint32_t a0, uint32_t a1, uint32_t a2, uint32_t a3,
                                          uint32_t b0, uint32_t b1) {
    asm volatile(
        "mma.sync.aligned.m16n8k16.row.col.f32.f16.f16.f32 "
        "{%0,%1,%2,%3}, {%4,%5,%6,%7}, {%8,%9}, {%0,%1,%2,%3};"
        : "+f"(c[0]), "+f"(c[1]), "+f"(c[2]), "+f"(c[3])
        : "r"(a0), "r"(a1), "r"(a2), "r"(a3), "r"(b0), "r"(b1));
}
__device__ __forceinline__ uint32_t packh2(float a, float b) {
    __half2 h = __floats2half2_rn(a, b);
    return *(uint32_t*)&h;
}

// ---------------------------------------------------------------------------
// Prep A: channel-major [B,C,N] -> point-major [B,N,72], float4 both sides
// ---------------------------------------------------------------------------
__global__ void prep_feats(const float* __restrict__ xyz, const float* __restrict__ feats) {
    __shared__ float tile[CP * 33];   // [c][32] stride-33
    const int b  = blockIdx.y;
    const int n0 = blockIdx.x * 32;
    for (int i = threadIdx.x; i < CP * 8; i += NTHR) {
        int c = i >> 3, q = i & 7;
        float4 v = make_float4(0.f, 0.f, 0.f, 0.f);
        if (c < 3)       v = *(const float4*)&xyz[((size_t)b * 3 + c) * NPTS + n0 + q * 4];
        else if (c < CF) v = *(const float4*)&feats[((size_t)b * CIN + (c - 3)) * NPTS + n0 + q * 4];
        tile[c * 33 + q * 4 + 0] = v.x;
        tile[c * 33 + q * 4 + 1] = v.y;
        tile[c * 33 + q * 4 + 2] = v.z;
        tile[c * 33 + q * 4 + 3] = v.w;
    }
    __syncthreads();
    for (int i = threadIdx.x; i < 32 * (CP / 4); i += NTHR) {
        int p = i / (CP / 4), q = i - p * (CP / 4);
        float4 v = make_float4(tile[(q*4+0)*33 + p], tile[(q*4+1)*33 + p],
                               tile[(q*4+2)*33 + p], tile[(q*4+3)*33 + p]);
        *(float4*)&g_featsCL[((size_t)b * NPTS + n0 + p) * CP + q * 4] = v;
    }
}

// ---------------------------------------------------------------------------
// Prep B: lin_w -> fp16 plane in A-frag order [ch][w][ks][lane][r]
// ---------------------------------------------------------------------------
__global__ void prep_lt(const float* __restrict__ lin_w) {
    int idx = blockIdx.x * NTHR + threadIdx.x;
    if (idx >= NCH * 4096) return;
    int r    = idx & 3;
    int lane = (idx >> 2) & 31;
    int ks   = (idx >> 7) & 3;
    int w    = (idx >> 9) & 7;
    int ch   = idx >> 12;
    int row = (lane >> 2) + ((r & 1) ? 8 : 0);
    int fk  = (lane & 3) * 2 + ((r >= 2) ? 8 : 0);
    int o   = w * 16 + row;
    float v[2];
#pragma unroll
    for (int e = 0; e < 2; e++) {
        int kg = ch * 64 + ks * 16 + fk + e;
        int wr = kg / 68, c = kg - wr * 68;
        v[e] = (c < CF) ? lin_w[(size_t)o * (16 * CF) + wr * CF + c] : 0.f;
    }
    g_LT[idx] = packh2(v[0], v[1]);
}

// ---------------------------------------------------------------------------
// pc_agg: gather + weight-net + inner MMA -> AGG fp16 (B-frag order) -> global
// 32 points per CTA, 8 warps x 4 points, 2 CTAs/SM
// ---------------------------------------------------------------------------
#define SMA_AGG 0            // 69632 = 4 blocks x 17408
#define SMA_WT  69632        // 8704
#define SMA_IDX 78336        // 512
#define SMA_PAR 78848        // 704
#define SMA_BYTES 79552

__device__ __forceinline__ void store_agg_pair(char* aggbase, int p, int w, int c, float v0, float v1) {
    if (c >= 68) return;                     // c even; pair (c, c+1)
    int kg = w * 68 + c;
    int ch = kg >> 6, kl = kg & 63;
    int ks = kl >> 4, kl2 = kl & 15;
    uint32_t off = (uint32_t)((p >> 3) * BLKB + ch * 1024 + ks * 256
                   + ((p & 7) * 4 + ((kl2 >> 1) & 3)) * 8 + (kl2 >> 3) * 4);
    *(__half2*)(aggbase + off) = __floats2half2_rn(v0, v1);
}

__global__ __launch_bounds__(NTHR, 2)
void pc_agg(const int*   __restrict__ knn,
            const float* __restrict__ w1, const float* __restrict__ b1,
            const float* __restrict__ w2, const float* __restrict__ b2)
{
    extern __shared__ __align__(128) char smem[];
    const uint32_t sb = smem_u32(smem);
    const int tid  = threadIdx.x;
    const int warp = tid >> 5;
    const int lane = tid & 31;
    const int b    = blockIdx.x >> 9;              // 512 CTAs per batch
    const int pb   = (blockIdx.x & 511) * 32;
    const size_t fb = (size_t)b * NPTS;

    float* sPar = (float*)(smem + SMA_PAR);
    if (tid < 176) {
        float v;
        if      (tid < 24)  v = w1[tid];
        else if (tid < 32)  v = b1[tid - 24];
        else if (tid < 160) v = w2[tid - 32];
        else                v = b2[tid - 160];
        sPar[tid] = v;
    }
    __syncthreads();

    float* myWt  = (float*)(smem + SMA_WT) + warp * 272;   // [k][17]
    int*   myIdx = (int*)(smem + SMA_IDX) + warp * 16;
    const float* W1 = sPar;       const float* B1 = sPar + 24;
    const float* W2 = sPar + 32;  const float* B2 = sPar + 160;
    const int kp   = (lane & 3) * 2;
    const int wrow = lane >> 2;
    const int cl   = lane >> 2;

    for (int r = 0; r < 4; r++) {
        const int p = warp * 4 + r;
        if (lane < 16) myIdx[lane] = knn[(fb + pb + p) * KNN + lane];
        __syncwarp();

        // weight-net: lane -> (k = lane/2, half), 8 of 16 w each
        {
            const float* crow = g_featsCL + (fb + pb + p) * CP;
            const float cx = crow[0], cy = crow[1], cz = crow[2];
            const int k = lane >> 1, half = lane & 1;
            const float* nrow = g_featsCL + (fb + myIdx[k]) * CP;
            const float dx = nrow[0] - cx, dy = nrow[1] - cy, dz = nrow[2] - cz;
            float h[8];
#pragma unroll
            for (int j = 0; j < 8; j++) {
                float v = W1[j*3]*dx + W1[j*3+1]*dy + W1[j*3+2]*dz + B1[j];
                h[j] = fmaxf(v, 0.1f * v);
            }
#pragma unroll
            for (int wv = 0; wv < 8; wv++) {
                int w = half * 8 + wv;
                float s = B2[w];
#pragma unroll
                for (int j = 0; j < 8; j++) s += W2[w*8 + j] * h[j];
                myWt[k * 17 + w] = fmaxf(s, 0.1f * s);
            }
        }
        __syncwarp();

        // A fragment: A[w][k] = myWt[k*17 + w]
        uint32_t a0 = packh2(myWt[kp*17 + wrow],         myWt[(kp+1)*17 + wrow]);
        uint32_t a1 = packh2(myWt[kp*17 + wrow + 8],     myWt[(kp+1)*17 + wrow + 8]);
        uint32_t a2 = packh2(myWt[(kp+8)*17 + wrow],     myWt[(kp+9)*17 + wrow]);
        uint32_t a3 = packh2(myWt[(kp+8)*17 + wrow + 8], myWt[(kp+9)*17 + wrow + 8]);

        // B fragments: feats[k][c]
        const float* r0p = g_featsCL + (fb + myIdx[kp])     * CP;
        const float* r1p = g_featsCL + (fb + myIdx[kp + 1]) * CP;
        const float* r2p = g_featsCL + (fb + myIdx[kp + 8]) * CP;
        const float* r3p = g_featsCL + (fb + myIdx[kp + 9]) * CP;
        uint32_t bb0[9], bb1[9];
#pragma unroll
        for (int cb = 0; cb < 9; cb++) {
            int c = cb * 8 + cl;
            bb0[cb] = packh2(r0p[c], r1p[c]);
            bb1[cb] = packh2(r2p[c], r3p[c]);
        }
#pragma unroll
        for (int cb = 0; cb < 9; cb++) {
            float c4[4] = {0.f, 0.f, 0.f, 0.f};
            mma16816h(c4, a0, a1, a2, a3, bb0[cb], bb1[cb]);
            int cc = cb * 8 + (lane & 3) * 2;
            store_agg_pair(smem, p, wrow,     cc, c4[0], c4[1]);
            store_agg_pair(smem, p, wrow + 8, cc, c4[2], c4[3]);
        }
        __syncwarp();
    }
    __syncthreads();
    asm volatile("fence.proxy.async.shared::cta;" ::: "memory");
    if (tid == 0) {
        bulk_st(g_AGG + (size_t)blockIdx.x * 4 * BLKB, sb + SMA_AGG, 4 * BLKB);
        asm volatile("cp.async.bulk.commit_group;" ::: "memory");
        asm volatile("cp.async.bulk.wait_group 0;" ::: "memory");
    }
}

// ---------------------------------------------------------------------------
// pc_gemm: out[128 x 64pts] tile; streams LT + AGG chunks, 4-stage pipeline
// ---------------------------------------------------------------------------
#define STAGE_B  24576       // 16K LT + 8K AGG per chunk
#define SMG_BAR  (4 * STAGE_B)
#define SMG_BYTES (SMG_BAR + 64)

__global__ __launch_bounds__(NTHR, 2)
void pc_gemm(const float* __restrict__ lin_b, float* __restrict__ out)
{
    extern __shared__ __align__(128) char smem[];
    const uint32_t sb = smem_u32(smem);
    const int tid  = threadIdx.x;
    const int warp = tid >> 5;
    const int lane = tid & 31;
    const int b    = blockIdx.x >> 8;              // 256 CTAs per batch
    const int pb   = (blockIdx.x & 255) * 64;
    const int gb0  = blockIdx.x * 8;               // first 8-pt AGG block

    if (tid == 0) {
#pragma unroll
        for (int s = 0; s < 4; s++) MBAR_INIT(sb + SMG_BAR + s * 8, 1);
    }
    __syncthreads();
    if (tid == 0) {
#pragma unroll
        for (int s = 0; s < 4; s++) {
            const uint32_t bar = sb + SMG_BAR + s * 8;
            const uint32_t stg = sb + s * STAGE_B;
            MBAR_EXPECT(bar, STAGE_B);
            bulk_cp(stg, g_LT + s * 4096, 16384, bar);
#pragma unroll
            for (int nb = 0; nb < 8; nb++)
                bulk_cp(stg + 16384 + nb * 1024,
                        g_AGG + (size_t)(gb0 + nb) * BLKB + s * 1024, 1024, bar);
        }
    }

    float acc[8][4];
#pragma unroll
    for (int nb = 0; nb < 8; nb++) { acc[nb][0] = acc[nb][1] = acc[nb][2] = acc[nb][3] = 0.f; }

    for (int ch = 0; ch < NCH; ch++) {
        const int s = ch & 3;
        mbar_wait(sb + SMG_BAR + s * 8, (ch >> 2) & 1);
        const uint32_t A  = sb + s * STAGE_B + warp * 2048;
        const uint32_t Bb = sb + s * STAGE_B + 16384 + lane * 8;
#pragma unroll
        for (int ks = 0; ks < 4; ks++) {
            uint32_t a0, a1, a2, a3;
            asm volatile("ld.shared.v4.u32 {%0,%1,%2,%3}, [%4];"
                         : "=r"(a0), "=r"(a1), "=r"(a2), "=r"(a3)
                         : "r"(A + ks * 512 + lane * 16));
#pragma unroll
            for (int nb = 0; nb < 8; nb++) {
                uint32_t b0, b1;
                asm volatile("ld.shared.v2.u32 {%0,%1}, [%2];"
                             : "=r"(b0), "=r"(b1)
                             : "r"(Bb + nb * 1024 + ks * 256));
                mma16816h(acc[nb], a0, a1, a2, a3, b0, b1);
            }
        }
        __syncthreads();
        if (tid == 0 && ch + 4 < NCH) {
            const uint32_t bar = sb + SMG_BAR + s * 8;
            const uint32_t stg = sb + s * STAGE_B;
            MBAR_EXPECT(bar, STAGE_B);
            bulk_cp(stg, g_LT + (ch + 4) * 4096, 16384, bar);
#pragma unroll
            for (int nb = 0; nb < 8; nb++)
                bulk_cp(stg + 16384 + nb * 1024,
                        g_AGG + (size_t)(gb0 + nb) * BLKB + (ch + 4) * 1024, 1024, bar);
        }
    }

    // epilogue: bias + leaky + float2 stores
    {
        const int wrow = lane >> 2, pc2 = (lane & 3) * 2;
#pragma unroll
        for (int h = 0; h < 2; h++) {
            const int o = warp * 16 + wrow + h * 8;
            const float bias = __ldg(&lin_b[o]);
            float* orow = out + ((size_t)b * COUT + o) * NPTS + pb;
#pragma unroll
            for (int nb = 0; nb < 8; nb++) {
                float x0 = acc[nb][h*2 + 0] + bias;
                float x1 = acc[nb][h*2 + 1] + bias;
                float2 v = make_float2(fmaxf(x0, 0.1f * x0), fmaxf(x1, 0.1f * x1));
                *(float2*)(orow + nb * 8 + pc2) = v;
            }
        }
    }
    __syncthreads();
    if (tid == 0) {
#pragma unroll
        for (int s = 0; s < 4; s++) MBAR_INVAL(sb + SMG_BAR + s * 8);
    }
}

// ---------------------------------------------------------------------------
extern "C" void kernel_launch(void* const* d_in, const int* in_sizes, int n_in,
                              void* d_out, int out_size) {
    const float* xyz   = (const float*)d_in[0];
    const float* feats = (const float*)d_in[1];
    const int*   knn   = (const int*)d_in[2];
    const float* w1    = (const float*)d_in[3];
    const float* b1    = (const float*)d_in[4];
    const float* w2    = (const float*)d_in[5];
    const float* b2    = (const float*)d_in[6];
    const float* lin_w = (const float*)d_in[7];
    const float* lin_b = (const float*)d_in[8];
    float* out = (float*)d_out;

    cudaFuncSetAttribute(pc_agg,  cudaFuncAttributeMaxDynamicSharedMemorySize, SMA_BYTES);
    cudaFuncSetAttribute(pc_gemm, cudaFuncAttributeMaxDynamicSharedMemorySize, SMG_BYTES);

    prep_feats<<<dim3(NPTS / 32, BB), NTHR>>>(xyz, feats);
    prep_lt<<<(NCH * 4096 + NTHR - 1) / NTHR, NTHR>>>(lin_w);
    pc_agg<<<BB * NPTS / 32, NTHR, SMA_BYTES>>>(knn, w1, b1, w2, b2);
    pc_gemm<<<BB * NPTS / 64, NTHR, SMG_BYTES>>>(lin_b, out);
}

// round 11
// speedup vs baseline: 8.5361x; 1.4931x over previous
#include <cuda_runtime.h>
#include <cuda_fp16.h>
#include <cstdint>

// ---------------- problem constants ----------------
#define BB    4
#define NPTS  16384
#define KNN   16
#define CIN   64
#define CF    67
#define CP    72          // padded channels (cols 67..71 zero)
#define COUT  128
#define NTHR  256
#define NCH   17          // 1088/64 k-chunks
#define BLKB  17408       // bytes of AGG per 8-point block: 17ch * 1024B

// ---------------- global scratch ----------------
__device__ float g_featsCL[(size_t)BB * NPTS * CP];     // [B][N][72] point-major fp32
// LT fp16, HMMA A-frag order: [ch][w][ks][lane][16B]
__device__ __align__(128) uint32_t g_LT[NCH * 4096];
// AGG fp16, paired-ks GEMM-B-frag order: [block(8192)][ch(17)][ks2(2)][lane(32)][16B]
__device__ __align__(128) unsigned char g_AGG[(size_t)8192 * BLKB];

// ---------------- PTX helpers ----------------
__device__ __forceinline__ uint32_t smem_u32(const void* p) {
    uint32_t a;
    asm("{ .reg .u64 t; cvta.to.shared.u64 t, %1; cvt.u32.u64 %0, t; }" : "=r"(a) : "l"(p));
    return a;
}
#define MBAR_INIT(a, c)   asm volatile("mbarrier.init.shared.b64 [%0], %1;" :: "r"(a), "r"(c) : "memory")
#define MBAR_EXPECT(a, n) asm volatile("mbarrier.arrive.expect_tx.shared.b64 _, [%0], %1;" :: "r"(a), "r"(n) : "memory")
#define MBAR_ARRIVE(a)    asm volatile("mbarrier.arrive.shared.b64 _, [%0];" :: "r"(a) : "memory")
#define MBAR_INVAL(a)     asm volatile("mbarrier.inval.shared.b64 [%0];" :: "r"(a) : "memory")

__device__ __forceinline__ void mbar_wait(uint32_t mbar, uint32_t parity) {
    asm volatile(
        "{\n\t.reg .pred P1;\n\t"
        "WAIT_LOOP_%=:\n\t"
        "mbarrier.try_wait.parity.acquire.cta.shared::cta.b64 P1, [%0], %1, 0x989680;\n\t"
        "@P1 bra.uni WAIT_DONE_%=;\n\t"
        "bra.uni WAIT_LOOP_%=;\n\t"
        "WAIT_DONE_%=:\n\t}"
        :: "r"(mbar), "r"(parity) : "memory");
}
__device__ __forceinline__ void bulk_cp(uint32_t dst_smem, const void* src_gmem, uint32_t bytes, uint32_t mbar) {
    asm volatile(
        "cp.async.bulk.shared::cluster.global.mbarrier::complete_tx::bytes [%0], [%1], %2, [%3];"
        :: "r"(dst_smem), "l"((unsigned long long)src_gmem), "r"(bytes), "r"(mbar) : "memory");
}
__device__ __forceinline__ void bulk_st(void* dst_gmem, uint32_t src_smem, uint32_t bytes) {
    asm volatile(
        "cp.async.bulk.global.shared::cta.bulk_group [%0], [%1], %2;"
        :: "l"((unsigned long long)dst_gmem), "r"(src_smem), "r"(bytes) : "memory");
}
__device__ __forceinline__ void mma16816h(float* c, uint32_t a0, uint32_t a1, uint32_t a2, uint32_t a3,
                                          uint32_t b0, uint32_t b1) {
    asm volatile(
        "mma.sync.aligned.m16n8k16.row.col.f32.f16.f16.f32 "
        "{%0,%1,%2,%3}, {%4,%5,%6,%7}, {%8,%9}, {%0,%1,%2,%3};"
        : "+f"(c[0]), "+f"(c[1]), "+f"(c[2]), "+f"(c[3])
        : "r"(a0), "r"(a1), "r"(a2), "r"(a3), "r"(b0), "r"(b1));
}
__device__ __forceinline__ uint32_t packh2(float a, float b) {
    __half2 h = __floats2half2_rn(a, b);
    return *(uint32_t*)&h;
}

// ---------------------------------------------------------------------------
// Prep A: channel-major [B,C,N] -> point-major [B,N,72], float4 both sides
// ---------------------------------------------------------------------------
__global__ void prep_feats(const float* __restrict__ xyz, const float* __restrict__ feats) {
    __shared__ float tile[CP * 33];   // [c][32] stride-33
    const int b  = blockIdx.y;
    const int n0 = blockIdx.x * 32;
    for (int i = threadIdx.x; i < CP * 8; i += NTHR) {
        int c = i >> 3, q = i & 7;
        float4 v = make_float4(0.f, 0.f, 0.f, 0.f);
        if (c < 3)       v = *(const float4*)&xyz[((size_t)b * 3 + c) * NPTS + n0 + q * 4];
        else if (c < CF) v = *(const float4*)&feats[((size_t)b * CIN + (c - 3)) * NPTS + n0 + q * 4];
        tile[c * 33 + q * 4 + 0] = v.x;
        tile[c * 33 + q * 4 + 1] = v.y;
        tile[c * 33 + q * 4 + 2] = v.z;
        tile[c * 33 + q * 4 + 3] = v.w;
    }
    __syncthreads();
    for (int i = threadIdx.x; i < 32 * (CP / 4); i += NTHR) {
        int p = i / (CP / 4), q = i - p * (CP / 4);
        float4 v = make_float4(tile[(q*4+0)*33 + p], tile[(q*4+1)*33 + p],
                               tile[(q*4+2)*33 + p], tile[(q*4+3)*33 + p]);
        *(float4*)&g_featsCL[((size_t)b * NPTS + n0 + p) * CP + q * 4] = v;
    }
}

// ---------------------------------------------------------------------------
// Prep B: lin_w -> fp16 plane in A-frag order [ch][w][ks][lane][r]
// ---------------------------------------------------------------------------
__global__ void prep_lt(const float* __restrict__ lin_w) {
    int idx = blockIdx.x * NTHR + threadIdx.x;
    if (idx >= NCH * 4096) return;
    int r    = idx & 3;
    int lane = (idx >> 2) & 31;
    int ks   = (idx >> 7) & 3;
    int w    = (idx >> 9) & 7;
    int ch   = idx >> 12;
    int row = (lane >> 2) + ((r & 1) ? 8 : 0);
    int fk  = (lane & 3) * 2 + ((r >= 2) ? 8 : 0);
    int o   = w * 16 + row;
    float v[2];
#pragma unroll
    for (int e = 0; e < 2; e++) {
        int kg = ch * 64 + ks * 16 + fk + e;
        int wr = kg / 68, c = kg - wr * 68;
        v[e] = (c < CF) ? lin_w[(size_t)o * (16 * CF) + wr * CF + c] : 0.f;
    }
    g_LT[idx] = packh2(v[0], v[1]);
}

// ---------------------------------------------------------------------------
// pc_agg: gather + weight-net + inner MMA -> AGG fp16 (paired-ks B-frag order)
// 32 points per CTA, 8 warps x 4 points, 2 CTAs/SM
// ---------------------------------------------------------------------------
#define SMA_AGG 0            // 69632 = 4 blocks x 17408
#define SMA_WT  69632        // 8704
#define SMA_IDX 78336        // 2048 (8 warps x 64 ints)
#define SMA_PAR 80384        // 704
#define SMA_BYTES 81088

__device__ __forceinline__ void store_agg_pair(char* aggbase, int p, int w, int c, float v0, float v1) {
    if (c >= 68) return;                     // c even; pair (c, c+1)
    int kg = w * 68 + c;
    int ch = kg >> 6, kl = kg & 63;
    int ks = kl >> 4, kl2 = kl & 15;
    uint32_t off = (uint32_t)((p >> 3) * BLKB + ch * 1024 + (ks >> 1) * 512
                   + ((p & 7) * 4 + ((kl2 >> 1) & 3)) * 16 + (ks & 1) * 8 + (kl2 >> 3) * 4);
    *(__half2*)(aggbase + off) = __floats2half2_rn(v0, v1);
}

__global__ __launch_bounds__(NTHR, 2)
void pc_agg(const int*   __restrict__ knn,
            const float* __restrict__ w1, const float* __restrict__ b1,
            const float* __restrict__ w2, const float* __restrict__ b2)
{
    extern __shared__ __align__(128) char smem[];
    const uint32_t sb = smem_u32(smem);
    const int tid  = threadIdx.x;
    const int warp = tid >> 5;
    const int lane = tid & 31;
    const int b    = blockIdx.x >> 9;              // 512 CTAs per batch
    const int pb   = (blockIdx.x & 511) * 32;
    const size_t fb = (size_t)b * NPTS;

    float* sPar = (float*)(smem + SMA_PAR);
    if (tid < 176) {
        float v;
        if      (tid < 24)  v = w1[tid];
        else if (tid < 32)  v = b1[tid - 24];
        else if (tid < 160) v = w2[tid - 32];
        else                v = b2[tid - 160];
        sPar[tid] = v;
    }
    __syncthreads();

    float* myWt  = (float*)(smem + SMA_WT) + warp * 272;   // [k][17]
    int*   myIdx = (int*)(smem + SMA_IDX) + warp * 64;
    const float* W1 = sPar;       const float* B1 = sPar + 24;
    const float* W2 = sPar + 32;  const float* B2 = sPar + 160;
    const int kp   = (lane & 3) * 2;
    const int wrow = lane >> 2;
    const int cl   = lane >> 2;

    // preload ALL knn indices for this warp's 4 points (4 LDGs/lane, high MLP)
    for (int i = lane; i < 64; i += 32)
        myIdx[i] = knn[(fb + pb + warp * 4 + (i >> 4)) * KNN + (i & 15)];
    __syncwarp();

    for (int r = 0; r < 4; r++) {
        const int p = warp * 4 + r;
        const int* idx = myIdx + r * 16;

        // ---- issue ALL gather loads first (36 B-frag + 6 weight-net floats) ----
        const float* r0p = g_featsCL + (fb + idx[kp])     * CP;
        const float* r1p = g_featsCL + (fb + idx[kp + 1]) * CP;
        const float* r2p = g_featsCL + (fb + idx[kp + 8]) * CP;
        const float* r3p = g_featsCL + (fb + idx[kp + 9]) * CP;
        float f0[9], f1[9], f2[9], f3[9];
#pragma unroll
        for (int cb = 0; cb < 9; cb++) {
            int c = cb * 8 + cl;
            f0[cb] = r0p[c]; f1[cb] = r1p[c]; f2[cb] = r2p[c]; f3[cb] = r3p[c];
        }
        const float* crow = g_featsCL + (fb + pb + p) * CP;
        const float cx = crow[0], cy = crow[1], cz = crow[2];
        const int kw = lane >> 1, half = lane & 1;
        const float* nrow = g_featsCL + (fb + idx[kw]) * CP;
        const float dx = nrow[0] - cx, dy = nrow[1] - cy, dz = nrow[2] - cz;

        // ---- weight-net (overlaps the in-flight gather loads) ----
        {
            float h[8];
#pragma unroll
            for (int j = 0; j < 8; j++) {
                float v = W1[j*3]*dx + W1[j*3+1]*dy + W1[j*3+2]*dz + B1[j];
                h[j] = fmaxf(v, 0.1f * v);
            }
#pragma unroll
            for (int wv = 0; wv < 8; wv++) {
                int w = half * 8 + wv;
                float s = B2[w];
#pragma unroll
                for (int j = 0; j < 8; j++) s += W2[w*8 + j] * h[j];
                myWt[kw * 17 + w] = fmaxf(s, 0.1f * s);
            }
        }
        __syncwarp();

        // A fragment: A[w][k] = myWt[k*17 + w]
        uint32_t a0 = packh2(myWt[kp*17 + wrow],         myWt[(kp+1)*17 + wrow]);
        uint32_t a1 = packh2(myWt[kp*17 + wrow + 8],     myWt[(kp+1)*17 + wrow + 8]);
        uint32_t a2 = packh2(myWt[(kp+8)*17 + wrow],     myWt[(kp+9)*17 + wrow]);
        uint32_t a3 = packh2(myWt[(kp+8)*17 + wrow + 8], myWt[(kp+9)*17 + wrow + 8]);

#pragma unroll
        for (int cb = 0; cb < 9; cb++) {
            uint32_t bb0 = packh2(f0[cb], f1[cb]);
            uint32_t bb1 = packh2(f2[cb], f3[cb]);
            float c4[4] = {0.f, 0.f, 0.f, 0.f};
            mma16816h(c4, a0, a1, a2, a3, bb0, bb1);
            int cc = cb * 8 + (lane & 3) * 2;
            store_agg_pair(smem, p, wrow,     cc, c4[0], c4[1]);
            store_agg_pair(smem, p, wrow + 8, cc, c4[2], c4[3]);
        }
        __syncwarp();
    }
    __syncthreads();
    asm volatile("fence.proxy.async.shared::cta;" ::: "memory");
    if (tid == 0) {
        bulk_st(g_AGG + (size_t)blockIdx.x * 4 * BLKB, sb + SMA_AGG, 4 * BLKB);
        asm volatile("cp.async.bulk.commit_group;" ::: "memory");
        asm volatile("cp.async.bulk.wait_group 0;" ::: "memory");
    }
}

// ---------------------------------------------------------------------------
// pc_gemm: out[128 x 64pts] tile; 4-stage LT+AGG pipeline, empty mbarriers
// ---------------------------------------------------------------------------
#define STAGE_B  24576       // 16K LT + 8K AGG per chunk
#define SMG_BAR  (4 * STAGE_B)           // full[0..3] then empty[0..3]
#define SMG_BYTES (SMG_BAR + 128)

__global__ __launch_bounds__(NTHR, 2)
void pc_gemm(const float* __restrict__ lin_b, float* __restrict__ out)
{
    extern __shared__ __align__(128) char smem[];
    const uint32_t sb = smem_u32(smem);
    const int tid  = threadIdx.x;
    const int warp = tid >> 5;
    const int lane = tid & 31;
    const int b    = blockIdx.x >> 8;              // 256 CTAs per batch
    const int pb   = (blockIdx.x & 255) * 64;
    const int gb0  = blockIdx.x * 8;               // first 8-pt AGG block

    if (tid == 0) {
#pragma unroll
        for (int s = 0; s < 4; s++) {
            MBAR_INIT(sb + SMG_BAR + s * 8, 1);        // full
            MBAR_INIT(sb + SMG_BAR + 32 + s * 8, 8);   // empty (8 warp arrivals)
        }
    }
    __syncthreads();
    if (tid == 0) {
#pragma unroll
        for (int s = 0; s < 4; s++) {
            const uint32_t bar = sb + SMG_BAR + s * 8;
            const uint32_t stg = sb + s * STAGE_B;
            MBAR_EXPECT(bar, STAGE_B);
            bulk_cp(stg, g_LT + s * 4096, 16384, bar);
#pragma unroll
            for (int nb = 0; nb < 8; nb++)
                bulk_cp(stg + 16384 + nb * 1024,
                        g_AGG + (size_t)(gb0 + nb) * BLKB + s * 1024, 1024, bar);
        }
    }

    float acc[8][4];
#pragma unroll
    for (int nb = 0; nb < 8; nb++) { acc[nb][0] = acc[nb][1] = acc[nb][2] = acc[nb][3] = 0.f; }

    for (int ch = 0; ch < NCH; ch++) {
        const int s = ch & 3;
        mbar_wait(sb + SMG_BAR + s * 8, (ch >> 2) & 1);
        const uint32_t A  = sb + s * STAGE_B + warp * 2048 + lane * 16;
        const uint32_t Bb = sb + s * STAGE_B + 16384 + lane * 16;
#pragma unroll
        for (int kp2 = 0; kp2 < 2; kp2++) {
            uint32_t ae0, ae1, ae2, ae3, ao0, ao1, ao2, ao3;
            asm volatile("ld.shared.v4.u32 {%0,%1,%2,%3}, [%4];"
                         : "=r"(ae0), "=r"(ae1), "=r"(ae2), "=r"(ae3)
                         : "r"(A + (2 * kp2) * 512));
            asm volatile("ld.shared.v4.u32 {%0,%1,%2,%3}, [%4];"
                         : "=r"(ao0), "=r"(ao1), "=r"(ao2), "=r"(ao3)
                         : "r"(A + (2 * kp2 + 1) * 512));
#pragma unroll
            for (int nb = 0; nb < 8; nb++) {
                uint32_t be0, be1, bo0, bo1;
                asm volatile("ld.shared.v4.u32 {%0,%1,%2,%3}, [%4];"
                             : "=r"(be0), "=r"(be1), "=r"(bo0), "=r"(bo1)
                             : "r"(Bb + nb * 1024 + kp2 * 512));
                mma16816h(acc[nb], ae0, ae1, ae2, ae3, be0, be1);
                mma16816h(acc[nb], ao0, ao1, ao2, ao3, bo0, bo1);
            }
        }
        if (lane == 0) MBAR_ARRIVE(sb + SMG_BAR + 32 + s * 8);
        if (tid == 0 && ch + 4 < NCH) {
            // recycle stage s once all 8 warps consumed chunk ch
            mbar_wait(sb + SMG_BAR + 32 + s * 8, (ch >> 2) & 1);
            const uint32_t bar = sb + SMG_BAR + s * 8;
            const uint32_t stg = sb + s * STAGE_B;
            MBAR_EXPECT(bar, STAGE_B);
            bulk_cp(stg, g_LT + (ch + 4) * 4096, 16384, bar);
#pragma unroll
            for (int nb = 0; nb < 8; nb++)
                bulk_cp(stg + 16384 + nb * 1024,
                        g_AGG + (size_t)(gb0 + nb) * BLKB + (ch + 4) * 1024, 1024, bar);
        }
    }

    // epilogue: bias + leaky + float2 stores
    {
        const int wrow = lane >> 2, pc2 = (lane & 3) * 2;
#pragma unroll
        for (int h = 0; h < 2; h++) {
            const int o = warp * 16 + wrow + h * 8;
            const float bias = __ldg(&lin_b[o]);
            float* orow = out + ((size_t)b * COUT + o) * NPTS + pb;
#pragma unroll
            for (int nb = 0; nb < 8; nb++) {
                float x0 = acc[nb][h*2 + 0] + bias;
                float x1 = acc[nb][h*2 + 1] + bias;
                float2 v = make_float2(fmaxf(x0, 0.1f * x0), fmaxf(x1, 0.1f * x1));
                *(float2*)(orow + nb * 8 + pc2) = v;
            }
        }
    }
    __syncthreads();
    if (tid == 0) {
#pragma unroll
        for (int s = 0; s < 4; s++) {
            MBAR_INVAL(sb + SMG_BAR + s * 8);
            MBAR_INVAL(sb + SMG_BAR + 32 + s * 8);
        }
    }
}

// ---------------------------------------------------------------------------
extern "C" void kernel_launch(void* const* d_in, const int* in_sizes, int n_in,
                              void* d_out, int out_size) {
    const float* xyz   = (const float*)d_in[0];
    const float* feats = (const float*)d_in[1];
    const int*   knn   = (const int*)d_in[2];
    const float* w1    = (const float*)d_in[3];
    const float* b1    = (const float*)d_in[4];
    const float* w2    = (const float*)d_in[5];
    const float* b2    = (const float*)d_in[6];
    const float* lin_w = (const float*)d_in[7];
    const float* lin_b = (const float*)d_in[8];
    float* out = (float*)d_out;

    cudaFuncSetAttribute(pc_agg,  cudaFuncAttributeMaxDynamicSharedMemorySize, SMA_BYTES);
    cudaFuncSetAttribute(pc_gemm, cudaFuncAttributeMaxDynamicSharedMemorySize, SMG_BYTES);

    prep_feats<<<dim3(NPTS / 32, BB), NTHR>>>(xyz, feats);
    prep_lt<<<(NCH * 4096 + NTHR - 1) / NTHR, NTHR>>>(lin_w);
    pc_agg<<<BB * NPTS / 32, NTHR, SMA_BYTES>>>(knn, w1, b1, w2, b2);
    pc_gemm<<<BB * NPTS / 64, NTHR, SMG_BYTES>>>(lin_b, out);
}

// round 12
// speedup vs baseline: 9.4037x; 1.1016x over previous
#include <cuda_runtime.h>
#include <cuda_fp16.h>
#include <cstdint>

// ---------------- problem constants ----------------
#define BB    4
#define NPTS  16384
#define KNN   16
#define CIN   64
#define CF    67
#define CP    72          // padded channels (cols 67..71 zero)
#define COUT  128
#define NTHR  256
#define NCH   17          // 1088/64 k-chunks
#define BLKB  17408       // bytes of AGG per 8-point block: 17ch * 1024B

// ---------------- global scratch ----------------
__device__ float g_featsCL[(size_t)BB * NPTS * CP];     // [B][N][72] point-major fp32
// LT fp16, HMMA A-frag order: [ch][w][ks][lane][16B]
__device__ __align__(128) uint32_t g_LT[NCH * 4096];
// AGG fp16, paired-ks GEMM-B-frag order: [block(8192)][ch(17)][ks2(2)][lane(32)][16B]
__device__ __align__(128) unsigned char g_AGG[(size_t)8192 * BLKB];

// ---------------- PTX helpers ----------------
__device__ __forceinline__ uint32_t smem_u32(const void* p) {
    uint32_t a;
    asm("{ .reg .u64 t; cvta.to.shared.u64 t, %1; cvt.u32.u64 %0, t; }" : "=r"(a) : "l"(p));
    return a;
}
#define MBAR_INIT(a, c)   asm volatile("mbarrier.init.shared.b64 [%0], %1;" :: "r"(a), "r"(c) : "memory")
#define MBAR_EXPECT(a, n) asm volatile("mbarrier.arrive.expect_tx.shared.b64 _, [%0], %1;" :: "r"(a), "r"(n) : "memory")
#define MBAR_ARRIVE(a)    asm volatile("mbarrier.arrive.shared.b64 _, [%0];" :: "r"(a) : "memory")
#define MBAR_INVAL(a)     asm volatile("mbarrier.inval.shared.b64 [%0];" :: "r"(a) : "memory")

__device__ __forceinline__ void mbar_wait(uint32_t mbar, uint32_t parity) {
    asm volatile(
        "{\n\t.reg .pred P1;\n\t"
        "WAIT_LOOP_%=:\n\t"
        "mbarrier.try_wait.parity.acquire.cta.shared::cta.b64 P1, [%0], %1, 0x989680;\n\t"
        "@P1 bra.uni WAIT_DONE_%=;\n\t"
        "bra.uni WAIT_LOOP_%=;\n\t"
        "WAIT_DONE_%=:\n\t}"
        :: "r"(mbar), "r"(parity) : "memory");
}
__device__ __forceinline__ void bulk_cp(uint32_t dst_smem, const void* src_gmem, uint32_t bytes, uint32_t mbar) {
    asm volatile(
        "cp.async.bulk.shared::cluster.global.mbarrier::complete_tx::bytes [%0], [%1], %2, [%3];"
        :: "r"(dst_smem), "l"((unsigned long long)src_gmem), "r"(bytes), "r"(mbar) : "memory");
}
__device__ __forceinline__ void bulk_st(void* dst_gmem, uint32_t src_smem, uint32_t bytes) {
    asm volatile(
        "cp.async.bulk.global.shared::cta.bulk_group [%0], [%1], %2;"
        :: "l"((unsigned long long)dst_gmem), "r"(src_smem), "r"(bytes) : "memory");
}
__device__ __forceinline__ void mma16816h(float* c, uint32_t a0, uint32_t a1, uint32_t a2, uint32_t a3,
                                          uint32_t b0, uint32_t b1) {
    asm volatile(
        "mma.sync.aligned.m16n8k16.row.col.f32.f16.f16.f32 "
        "{%0,%1,%2,%3}, {%4,%5,%6,%7}, {%8,%9}, {%0,%1,%2,%3};"
        : "+f"(c[0]), "+f"(c[1]), "+f"(c[2]), "+f"(c[3])
        : "r"(a0), "r"(a1), "r"(a2), "r"(a3), "r"(b0), "r"(b1));
}
__device__ __forceinline__ uint32_t packh2(float a, float b) {
    __half2 h = __floats2half2_rn(a, b);
    return *(uint32_t*)&h;
}

// ---------------------------------------------------------------------------
// Prep A: channel-major [B,C,N] -> point-major [B,N,72], float4 both sides
// ---------------------------------------------------------------------------
__global__ void prep_feats(const float* __restrict__ xyz, const float* __restrict__ feats) {
    __shared__ float tile[CP * 33];   // [c][32] stride-33
    const int b  = blockIdx.y;
    const int n0 = blockIdx.x * 32;
    for (int i = threadIdx.x; i < CP * 8; i += NTHR) {
        int c = i >> 3, q = i & 7;
        float4 v = make_float4(0.f, 0.f, 0.f, 0.f);
        if (c < 3)       v = *(const float4*)&xyz[((size_t)b * 3 + c) * NPTS + n0 + q * 4];
        else if (c < CF) v = *(const float4*)&feats[((size_t)b * CIN + (c - 3)) * NPTS + n0 + q * 4];
        tile[c * 33 + q * 4 + 0] = v.x;
        tile[c * 33 + q * 4 + 1] = v.y;
        tile[c * 33 + q * 4 + 2] = v.z;
        tile[c * 33 + q * 4 + 3] = v.w;
    }
    __syncthreads();
    for (int i = threadIdx.x; i < 32 * (CP / 4); i += NTHR) {
        int p = i / (CP / 4), q = i - p * (CP / 4);
        float4 v = make_float4(tile[(q*4+0)*33 + p], tile[(q*4+1)*33 + p],
                               tile[(q*4+2)*33 + p], tile[(q*4+3)*33 + p]);
        *(float4*)&g_featsCL[((size_t)b * NPTS + n0 + p) * CP + q * 4] = v;
    }
}

// ---------------------------------------------------------------------------
// Prep B: lin_w -> fp16 plane in A-frag order [ch][w][ks][lane][r]
// ---------------------------------------------------------------------------
__global__ void prep_lt(const float* __restrict__ lin_w) {
    int idx = blockIdx.x * NTHR + threadIdx.x;
    if (idx >= NCH * 4096) return;
    int r    = idx & 3;
    int lane = (idx >> 2) & 31;
    int ks   = (idx >> 7) & 3;
    int w    = (idx >> 9) & 7;
    int ch   = idx >> 12;
    int row = (lane >> 2) + ((r & 1) ? 8 : 0);
    int fk  = (lane & 3) * 2 + ((r >= 2) ? 8 : 0);
    int o   = w * 16 + row;
    float v[2];
#pragma unroll
    for (int e = 0; e < 2; e++) {
        int kg = ch * 64 + ks * 16 + fk + e;
        int wr = kg / 68, c = kg - wr * 68;
        v[e] = (c < CF) ? lin_w[(size_t)o * (16 * CF) + wr * CF + c] : 0.f;
    }
    g_LT[idx] = packh2(v[0], v[1]);
}

// ---------------------------------------------------------------------------
// pc_agg: gather + weight-net + inner MMA -> AGG fp16 (paired-ks B-frag order)
// 16 points per CTA, 8 warps x 2 points, 3 CTAs/SM
// ---------------------------------------------------------------------------
#define SMA_AGG 0            // 34816 = 2 blocks x 17408
#define SMA_WT  34816        // 8704
#define SMA_IDX 43520        // 1024 (8 warps x 32 ints)
#define SMA_PAR 44544        // 704
#define SMA_BYTES 45248

__device__ __forceinline__ void store_agg_pair(char* aggbase, int p, int w, int c, float v0, float v1) {
    if (c >= 68) return;                     // c even; pair (c, c+1)
    int kg = w * 68 + c;
    int ch = kg >> 6, kl = kg & 63;
    int ks = kl >> 4, kl2 = kl & 15;
    uint32_t off = (uint32_t)((p >> 3) * BLKB + ch * 1024 + (ks >> 1) * 512
                   + ((p & 7) * 4 + ((kl2 >> 1) & 3)) * 16 + (ks & 1) * 8 + (kl2 >> 3) * 4);
    *(__half2*)(aggbase + off) = __floats2half2_rn(v0, v1);
}

__global__ __launch_bounds__(NTHR, 3)
void pc_agg(const int*   __restrict__ knn,
            const float* __restrict__ w1, const float* __restrict__ b1,
            const float* __restrict__ w2, const float* __restrict__ b2)
{
    extern __shared__ __align__(128) char smem[];
    const uint32_t sb = smem_u32(smem);
    const int tid  = threadIdx.x;
    const int warp = tid >> 5;
    const int lane = tid & 31;
    const int b    = blockIdx.x >> 10;             // 1024 CTAs per batch
    const int pb   = (blockIdx.x & 1023) * 16;
    const size_t fb = (size_t)b * NPTS;

    float* sPar = (float*)(smem + SMA_PAR);
    if (tid < 176) {
        float v;
        if      (tid < 24)  v = w1[tid];
        else if (tid < 32)  v = b1[tid - 24];
        else if (tid < 160) v = w2[tid - 32];
        else                v = b2[tid - 160];
        sPar[tid] = v;
    }
    __syncthreads();

    float* myWt  = (float*)(smem + SMA_WT) + warp * 272;   // [k][17]
    int*   myIdx = (int*)(smem + SMA_IDX) + warp * 32;
    const float* W1 = sPar;       const float* B1 = sPar + 24;
    const float* W2 = sPar + 32;  const float* B2 = sPar + 160;
    const int kp   = (lane & 3) * 2;
    const int wrow = lane >> 2;
    const int cl   = lane >> 2;

    // preload this warp's 2 points x 16 knn indices (1 LDG/lane)
    myIdx[lane] = knn[(fb + pb + warp * 2 + (lane >> 4)) * KNN + (lane & 15)];
    __syncwarp();

    for (int r = 0; r < 2; r++) {
        const int p = warp * 2 + r;
        const int* idx = myIdx + r * 16;

        // ---- issue ALL gather loads first (36 B-frag + weight-net inputs) ----
        const float* r0p = g_featsCL + (fb + idx[kp])     * CP;
        const float* r1p = g_featsCL + (fb + idx[kp + 1]) * CP;
        const float* r2p = g_featsCL + (fb + idx[kp + 8]) * CP;
        const float* r3p = g_featsCL + (fb + idx[kp + 9]) * CP;
        float f0[9], f1[9], f2[9], f3[9];
#pragma unroll
        for (int cb = 0; cb < 9; cb++) {
            int c = cb * 8 + cl;
            f0[cb] = r0p[c]; f1[cb] = r1p[c]; f2[cb] = r2p[c]; f3[cb] = r3p[c];
        }
        const float* crow = g_featsCL + (fb + pb + p) * CP;
        const float cx = crow[0], cy = crow[1], cz = crow[2];
        const int kw = lane >> 1, half = lane & 1;
        const float* nrow = g_featsCL + (fb + idx[kw]) * CP;
        const float dx = nrow[0] - cx, dy = nrow[1] - cy, dz = nrow[2] - cz;

        // ---- weight-net (overlaps the in-flight gather loads) ----
        {
            float h[8];
#pragma unroll
            for (int j = 0; j < 8; j++) {
                float v = W1[j*3]*dx + W1[j*3+1]*dy + W1[j*3+2]*dz + B1[j];
                h[j] = fmaxf(v, 0.1f * v);
            }
#pragma unroll
            for (int wv = 0; wv < 8; wv++) {
                int w = half * 8 + wv;
                float s = B2[w];
#pragma unroll
                for (int j = 0; j < 8; j++) s += W2[w*8 + j] * h[j];
                myWt[kw * 17 + w] = fmaxf(s, 0.1f * s);
            }
        }
        __syncwarp();

        // A fragment: A[w][k] = myWt[k*17 + w]
        uint32_t a0 = packh2(myWt[kp*17 + wrow],         myWt[(kp+1)*17 + wrow]);
        uint32_t a1 = packh2(myWt[kp*17 + wrow + 8],     myWt[(kp+1)*17 + wrow + 8]);
        uint32_t a2 = packh2(myWt[(kp+8)*17 + wrow],     myWt[(kp+9)*17 + wrow]);
        uint32_t a3 = packh2(myWt[(kp+8)*17 + wrow + 8], myWt[(kp+9)*17 + wrow + 8]);

#pragma unroll
        for (int cb = 0; cb < 9; cb++) {
            uint32_t bb0 = packh2(f0[cb], f1[cb]);
            uint32_t bb1 = packh2(f2[cb], f3[cb]);
            float c4[4] = {0.f, 0.f, 0.f, 0.f};
            mma16816h(c4, a0, a1, a2, a3, bb0, bb1);
            int cc = cb * 8 + (lane & 3) * 2;
            store_agg_pair(smem, p, wrow,     cc, c4[0], c4[1]);
            store_agg_pair(smem, p, wrow + 8, cc, c4[2], c4[3]);
        }
        __syncwarp();
    }
    __syncthreads();
    asm volatile("fence.proxy.async.shared::cta;" ::: "memory");
    if (tid == 0) {
        bulk_st(g_AGG + (size_t)blockIdx.x * 2 * BLKB, sb + SMA_AGG, 2 * BLKB);
        asm volatile("cp.async.bulk.commit_group;" ::: "memory");
        asm volatile("cp.async.bulk.wait_group 0;" ::: "memory");
    }
}

// ---------------------------------------------------------------------------
// pc_gemm: out[128 x 64pts]; 2-stage x 2-chunk pipeline (9 waits instead of 17)
// ---------------------------------------------------------------------------
#define SUB_B    24576       // per chunk: 16K LT + 8K AGG
#define STAGE_B  (2 * SUB_B) // 49152
#define SMG_BAR  (2 * STAGE_B)          // full[0..1] then empty[0..1]
#define SMG_BYTES (SMG_BAR + 128)
#define NSTEP    9           // ceil(17/2)

__global__ __launch_bounds__(NTHR, 2)
void pc_gemm(const float* __restrict__ lin_b, float* __restrict__ out)
{
    extern __shared__ __align__(128) char smem[];
    const uint32_t sb = smem_u32(smem);
    const int tid  = threadIdx.x;
    const int warp = tid >> 5;
    const int lane = tid & 31;
    const int b    = blockIdx.x >> 8;              // 256 CTAs per batch
    const int pb   = (blockIdx.x & 255) * 64;
    const int gb0  = blockIdx.x * 8;               // first 8-pt AGG block

    if (tid == 0) {
#pragma unroll
        for (int s = 0; s < 2; s++) {
            MBAR_INIT(sb + SMG_BAR + s * 8, 1);        // full
            MBAR_INIT(sb + SMG_BAR + 16 + s * 8, 8);   // empty (8 warp arrivals)
        }
    }
    __syncthreads();
    // prefetch steps 0,1 (chunks 0..3)
    if (tid == 0) {
#pragma unroll
        for (int s = 0; s < 2; s++) {
            const uint32_t bar = sb + SMG_BAR + s * 8;
            MBAR_EXPECT(bar, STAGE_B);
#pragma unroll
            for (int u = 0; u < 2; u++) {
                const int ch = s * 2 + u;
                const uint32_t stg = sb + s * STAGE_B + u * SUB_B;
                bulk_cp(stg, g_LT + ch * 4096, 16384, bar);
#pragma unroll
                for (int nb = 0; nb < 8; nb++)
                    bulk_cp(stg + 16384 + nb * 1024,
                            g_AGG + (size_t)(gb0 + nb) * BLKB + ch * 1024, 1024, bar);
            }
        }
    }

    float acc[8][4];
#pragma unroll
    for (int nb = 0; nb < 8; nb++) { acc[nb][0] = acc[nb][1] = acc[nb][2] = acc[nb][3] = 0.f; }

    for (int step = 0; step < NSTEP; step++) {
        const int s = step & 1;
        const int phase = (step >> 1) & 1;
        mbar_wait(sb + SMG_BAR + s * 8, phase);
#pragma unroll
        for (int u = 0; u < 2; u++) {
            const int ch = step * 2 + u;
            if (ch >= NCH) break;
            const uint32_t A  = sb + s * STAGE_B + u * SUB_B + warp * 2048 + lane * 16;
            const uint32_t Bb = sb + s * STAGE_B + u * SUB_B + 16384 + lane * 16;
#pragma unroll
            for (int kp2 = 0; kp2 < 2; kp2++) {
                uint32_t ae0, ae1, ae2, ae3, ao0, ao1, ao2, ao3;
                asm volatile("ld.shared.v4.u32 {%0,%1,%2,%3}, [%4];"
                             : "=r"(ae0), "=r"(ae1), "=r"(ae2), "=r"(ae3)
                             : "r"(A + (2 * kp2) * 512));
                asm volatile("ld.shared.v4.u32 {%0,%1,%2,%3}, [%4];"
                             : "=r"(ao0), "=r"(ao1), "=r"(ao2), "=r"(ao3)
                             : "r"(A + (2 * kp2 + 1) * 512));
#pragma unroll
                for (int nb = 0; nb < 8; nb++) {
                    uint32_t be0, be1, bo0, bo1;
                    asm volatile("ld.shared.v4.u32 {%0,%1,%2,%3}, [%4];"
                                 : "=r"(be0), "=r"(be1), "=r"(bo0), "=r"(bo1)
                                 : "r"(Bb + nb * 1024 + kp2 * 512));
                    mma16816h(acc[nb], ae0, ae1, ae2, ae3, be0, be1);
                    mma16816h(acc[nb], ao0, ao1, ao2, ao3, bo0, bo1);
                }
            }
        }
        if (lane == 0) MBAR_ARRIVE(sb + SMG_BAR + 16 + s * 8);
        if (tid == 0 && step + 2 < NSTEP) {
            // recycle stage s once all 8 warps consumed this step
            mbar_wait(sb + SMG_BAR + 16 + s * 8, phase);
            const uint32_t bar = sb + SMG_BAR + s * 8;
            const int c0 = (step + 2) * 2;
            const int nsub = (c0 + 1 < NCH) ? 2 : 1;
            MBAR_EXPECT(bar, nsub * SUB_B);
            for (int u = 0; u < nsub; u++) {
                const int ch = c0 + u;
                const uint32_t stg = sb + s * STAGE_B + u * SUB_B;
                bulk_cp(stg, g_LT + ch * 4096, 16384, bar);
#pragma unroll
                for (int nb = 0; nb < 8; nb++)
                    bulk_cp(stg + 16384 + nb * 1024,
                            g_AGG + (size_t)(gb0 + nb) * BLKB + ch * 1024, 1024, bar);
            }
        }
    }

    // epilogue: bias + leaky + float2 stores
    {
        const int wrow = lane >> 2, pc2 = (lane & 3) * 2;
#pragma unroll
        for (int h = 0; h < 2; h++) {
            const int o = warp * 16 + wrow + h * 8;
            const float bias = __ldg(&lin_b[o]);
            float* orow = out + ((size_t)b * COUT + o) * NPTS + pb;
#pragma unroll
            for (int nb = 0; nb < 8; nb++) {
                float x0 = acc[nb][h*2 + 0] + bias;
                float x1 = acc[nb][h*2 + 1] + bias;
                float2 v = make_float2(fmaxf(x0, 0.1f * x0), fmaxf(x1, 0.1f * x1));
                *(float2*)(orow + nb * 8 + pc2) = v;
            }
        }
    }
    __syncthreads();
    if (tid == 0) {
#pragma unroll
        for (int s = 0; s < 2; s++) {
            MBAR_INVAL(sb + SMG_BAR + s * 8);
            MBAR_INVAL(sb + SMG_BAR + 16 + s * 8);
        }
    }
}

// ---------------------------------------------------------------------------
extern "C" void kernel_launch(void* const* d_in, const int* in_sizes, int n_in,
                              void* d_out, int out_size) {
    const float* xyz   = (const float*)d_in[0];
    const float* feats = (const float*)d_in[1];
    const int*   knn   = (const int*)d_in[2];
    const float* w1    = (const float*)d_in[3];
    const float* b1    = (const float*)d_in[4];
    const float* w2    = (const float*)d_in[5];
    const float* b2    = (const float*)d_in[6];
    const float* lin_w = (const float*)d_in[7];
    const float* lin_b = (const float*)d_in[8];
    float* out = (float*)d_out;

    cudaFuncSetAttribute(pc_agg,  cudaFuncAttributeMaxDynamicSharedMemorySize, SMA_BYTES);
    cudaFuncSetAttribute(pc_gemm, cudaFuncAttributeMaxDynamicSharedMemorySize, SMG_BYTES);

    prep_feats<<<dim3(NPTS / 32, BB), NTHR>>>(xyz, feats);
    prep_lt<<<(NCH * 4096 + NTHR - 1) / NTHR, NTHR>>>(lin_w);
    pc_agg<<<BB * NPTS / 16, NTHR, SMA_BYTES>>>(knn, w1, b1, w2, b2);
    pc_gemm<<<BB * NPTS / 64, NTHR, SMG_BYTES>>>(lin_b, out);
}